// round 1
// baseline (speedup 1.0000x reference)
#include <cuda_runtime.h>
#include <cuda_bf16.h>
#include <math.h>

// Problem constants
#define BATCH 2
#define SEQ   4096
#define DMODEL 512
#define NHEAD 8
#define HDIM  64
#define MROWS (BATCH*SEQ)   // 8192
#define MAXREL 2

// Scratch (device globals — no runtime allocation allowed)
__device__ float g_Q[MROWS * DMODEL];
__device__ float g_K[MROWS * DMODEL];
__device__ float g_V[MROWS * DMODEL];
__device__ float g_A[MROWS * DMODEL];

// ---------------------------------------------------------------------------
// GEMM: C[M,512] = X[M,512] @ W^T[512,512] + bias   (W row-major [out,in])
// BM=BN=64, BK=16, 256 threads, 4x4 micro-tile per thread.
// ---------------------------------------------------------------------------
__global__ __launch_bounds__(256) void gemm_xwt(const float* __restrict__ X,
                                                const float* __restrict__ W,
                                                const float* __restrict__ bias,
                                                float* __restrict__ C)
{
    __shared__ float As[16][68];   // As[k][m]
    __shared__ float Bs[16][68];   // Bs[k][n]

    const int tid = threadIdx.x;
    const int ty = tid >> 4, tx = tid & 15;
    const int m0 = blockIdx.y * 64;
    const int n0 = blockIdx.x * 64;

    const int lr = tid >> 2;            // 0..63
    const int lk4 = (tid & 3) * 4;      // 0,4,8,12

    float acc[4][4];
#pragma unroll
    for (int i = 0; i < 4; i++)
#pragma unroll
        for (int j = 0; j < 4; j++) acc[i][j] = 0.f;

    const float* Xg = X + (size_t)(m0 + lr) * DMODEL + lk4;
    const float* Wg = W + (size_t)(n0 + lr) * DMODEL + lk4;

    for (int k0 = 0; k0 < DMODEL; k0 += 16) {
        float4 xa = *(const float4*)(Xg + k0);
        float4 wb = *(const float4*)(Wg + k0);
        As[lk4 + 0][lr] = xa.x; As[lk4 + 1][lr] = xa.y;
        As[lk4 + 2][lr] = xa.z; As[lk4 + 3][lr] = xa.w;
        Bs[lk4 + 0][lr] = wb.x; Bs[lk4 + 1][lr] = wb.y;
        Bs[lk4 + 2][lr] = wb.z; Bs[lk4 + 3][lr] = wb.w;
        __syncthreads();
#pragma unroll
        for (int kk = 0; kk < 16; kk++) {
            float4 a = *(const float4*)&As[kk][ty * 4];
            float4 b = *(const float4*)&Bs[kk][tx * 4];
            acc[0][0] += a.x * b.x; acc[0][1] += a.x * b.y; acc[0][2] += a.x * b.z; acc[0][3] += a.x * b.w;
            acc[1][0] += a.y * b.x; acc[1][1] += a.y * b.y; acc[1][2] += a.y * b.z; acc[1][3] += a.y * b.w;
            acc[2][0] += a.z * b.x; acc[2][1] += a.z * b.y; acc[2][2] += a.z * b.z; acc[2][3] += a.z * b.w;
            acc[3][0] += a.w * b.x; acc[3][1] += a.w * b.y; acc[3][2] += a.w * b.z; acc[3][3] += a.w * b.w;
        }
        __syncthreads();
    }

    float4 bv = *(const float4*)(bias + n0 + tx * 4);
#pragma unroll
    for (int i = 0; i < 4; i++) {
        float4 out;
        out.x = acc[i][0] + bv.x;
        out.y = acc[i][1] + bv.y;
        out.z = acc[i][2] + bv.z;
        out.w = acc[i][3] + bv.w;
        *(float4*)(C + (size_t)(m0 + ty * 4 + i) * DMODEL + n0 + tx * 4) = out;
    }
}

// ---------------------------------------------------------------------------
// Flash attention with relative-position bias.
// One block = (batch b, head h, 64-row query tile). 256 threads.
// Smem: Qs/Ks transposed [hd][row] (pitch 68), Vs [key][hd], Ps [row][key].
// ---------------------------------------------------------------------------
#define PT 68
#define ATTN_SMEM ((4 * 64 * PT + 3 * 64) * sizeof(float))

__global__ __launch_bounds__(256) void attn_kernel(const float* __restrict__ Q,
                                                   const float* __restrict__ K,
                                                   const float* __restrict__ V,
                                                   const float* __restrict__ relpos,
                                                   float* __restrict__ Out)
{
    extern __shared__ float sm[];
    float* Qs = sm;                    // [64 hd][PT rows]
    float* Ks = Qs + 64 * PT;          // [64 hd][PT cols]
    float* Vs = Ks + 64 * PT;          // [64 key][PT hd]
    float* Ps = Vs + 64 * PT;          // [64 row][PT col]
    float* mrow = Ps + 64 * PT;        // [64]
    float* lrow = mrow + 64;           // [64]
    float* rsc  = lrow + 64;           // [64]

    const int tid = threadIdx.x;
    const int ty = tid >> 4, tx = tid & 15;
    const int r0 = ty * 4, c0 = tx * 4;
    const int b = blockIdx.z, h = blockIdx.y;
    const int q0 = blockIdx.x * 64;

    const int lr = tid >> 2;           // 0..63
    const int lc4 = (tid & 3) * 4;     // 0,4,8,12

    // rel-pos bias for this head
    float rb[5];
#pragma unroll
    for (int j = 0; j < 5; j++) rb[j] = relpos[h * 5 + j];
    const float bneg = rb[0], bpos = rb[4];

    // Load Q tile (transposed into Qs, pre-scaled by 1/sqrt(64) = 0.125)
    {
        const float* Qg = Q + (size_t)(b * SEQ + q0 + lr) * DMODEL + h * HDIM;
#pragma unroll
        for (int ii = 0; ii < 4; ii++) {
            int hd = lc4 + ii * 16;
            float4 v = *(const float4*)(Qg + hd);
            Qs[(hd + 0) * PT + lr] = v.x * 0.125f;
            Qs[(hd + 1) * PT + lr] = v.y * 0.125f;
            Qs[(hd + 2) * PT + lr] = v.z * 0.125f;
            Qs[(hd + 3) * PT + lr] = v.w * 0.125f;
        }
    }
    if (tid < 64) { mrow[tid] = -1e30f; lrow[tid] = 0.f; }

    float o[4][4];
#pragma unroll
    for (int i = 0; i < 4; i++)
#pragma unroll
        for (int j = 0; j < 4; j++) o[i][j] = 0.f;

    for (int kt = 0; kt < SEQ / 64; kt++) {
        const int k0 = kt * 64;
        __syncthreads();   // protect Ks/Vs/Ps from previous iteration readers

        // Load K (transposed) and V (direct)
        {
            const float* Kg = K + (size_t)(b * SEQ + k0 + lr) * DMODEL + h * HDIM;
            const float* Vg = V + (size_t)(b * SEQ + k0 + lr) * DMODEL + h * HDIM;
#pragma unroll
            for (int ii = 0; ii < 4; ii++) {
                int hd = lc4 + ii * 16;
                float4 kv = *(const float4*)(Kg + hd);
                Ks[(hd + 0) * PT + lr] = kv.x;
                Ks[(hd + 1) * PT + lr] = kv.y;
                Ks[(hd + 2) * PT + lr] = kv.z;
                Ks[(hd + 3) * PT + lr] = kv.w;
                float4 vv = *(const float4*)(Vg + hd);
                *(float4*)&Vs[lr * PT + hd] = vv;
            }
        }
        __syncthreads();

        // S = (Q/8) @ K^T   (4x4 per thread)
        float s[4][4];
#pragma unroll
        for (int i = 0; i < 4; i++)
#pragma unroll
            for (int j = 0; j < 4; j++) s[i][j] = 0.f;
#pragma unroll 8
        for (int d = 0; d < 64; d++) {
            float4 a = *(const float4*)&Qs[d * PT + r0];
            float4 bb = *(const float4*)&Ks[d * PT + c0];
            s[0][0] += a.x * bb.x; s[0][1] += a.x * bb.y; s[0][2] += a.x * bb.z; s[0][3] += a.x * bb.w;
            s[1][0] += a.y * bb.x; s[1][1] += a.y * bb.y; s[1][2] += a.y * bb.z; s[1][3] += a.y * bb.w;
            s[2][0] += a.z * bb.x; s[2][1] += a.z * bb.y; s[2][2] += a.z * bb.z; s[2][3] += a.z * bb.w;
            s[3][0] += a.w * bb.x; s[3][1] += a.w * bb.y; s[3][2] += a.w * bb.z; s[3][3] += a.w * bb.w;
        }

        // Relative position bias (uniform per block branch)
        const int relmin = k0 - q0 - 63;
        const int relmax = k0 + 63 - q0;
        if (relmin >= MAXREL) {
#pragma unroll
            for (int i = 0; i < 4; i++)
#pragma unroll
                for (int j = 0; j < 4; j++) s[i][j] += bpos;
        } else if (relmax <= -MAXREL) {
#pragma unroll
            for (int i = 0; i < 4; i++)
#pragma unroll
                for (int j = 0; j < 4; j++) s[i][j] += bneg;
        } else {
#pragma unroll
            for (int i = 0; i < 4; i++)
#pragma unroll
                for (int j = 0; j < 4; j++) {
                    int rel = (k0 + c0 + j) - (q0 + r0 + i);
                    int idx = rel < -MAXREL ? 0 : (rel > MAXREL ? 4 : rel + MAXREL);
                    s[i][j] += rb[idx];
                }
        }

        // Write scores to Ps
#pragma unroll
        for (int i = 0; i < 4; i++) {
            float4 out = make_float4(s[i][0], s[i][1], s[i][2], s[i][3]);
            *(float4*)&Ps[(r0 + i) * PT + c0] = out;
        }
        __syncthreads();

        // Online softmax: warp w owns rows w*8 .. w*8+7
        {
            const int wid = tid >> 5, lane = tid & 31;
#pragma unroll
            for (int rr = 0; rr < 8; rr++) {
                const int row = wid * 8 + rr;
                float v0 = Ps[row * PT + lane];
                float v1 = Ps[row * PT + lane + 32];
                float mx = fmaxf(v0, v1);
#pragma unroll
                for (int off = 16; off > 0; off >>= 1)
                    mx = fmaxf(mx, __shfl_xor_sync(0xFFFFFFFFu, mx, off));
                const float mold = mrow[row];
                const float mnew = fmaxf(mold, mx);
                float p0 = __expf(v0 - mnew);
                float p1 = __expf(v1 - mnew);
                Ps[row * PT + lane] = p0;
                Ps[row * PT + lane + 32] = p1;
                float sum = p0 + p1;
#pragma unroll
                for (int off = 16; off > 0; off >>= 1)
                    sum += __shfl_xor_sync(0xFFFFFFFFu, sum, off);
                if (lane == 0) {
                    const float sc = __expf(mold - mnew);
                    rsc[row] = sc;
                    lrow[row] = lrow[row] * sc + sum;
                    mrow[row] = mnew;
                }
            }
        }
        __syncthreads();

        // O = O*rescale + P @ V
#pragma unroll
        for (int i = 0; i < 4; i++) {
            const float rs = rsc[r0 + i];
            o[i][0] *= rs; o[i][1] *= rs; o[i][2] *= rs; o[i][3] *= rs;
        }
#pragma unroll 4
        for (int k = 0; k < 64; k++) {
            float4 v4 = *(const float4*)&Vs[k * PT + c0];
            float p0 = Ps[(r0 + 0) * PT + k];
            float p1 = Ps[(r0 + 1) * PT + k];
            float p2 = Ps[(r0 + 2) * PT + k];
            float p3 = Ps[(r0 + 3) * PT + k];
            o[0][0] += p0 * v4.x; o[0][1] += p0 * v4.y; o[0][2] += p0 * v4.z; o[0][3] += p0 * v4.w;
            o[1][0] += p1 * v4.x; o[1][1] += p1 * v4.y; o[1][2] += p1 * v4.z; o[1][3] += p1 * v4.w;
            o[2][0] += p2 * v4.x; o[2][1] += p2 * v4.y; o[2][2] += p2 * v4.z; o[2][3] += p2 * v4.w;
            o[3][0] += p3 * v4.x; o[3][1] += p3 * v4.y; o[3][2] += p3 * v4.z; o[3][3] += p3 * v4.w;
        }
    }

    // Epilogue: normalize and store as [b, s, h*64+hd]
#pragma unroll
    for (int i = 0; i < 4; i++) {
        const float inv = 1.f / lrow[r0 + i];
        float4 out = make_float4(o[i][0] * inv, o[i][1] * inv, o[i][2] * inv, o[i][3] * inv);
        *(float4*)(Out + (size_t)(b * SEQ + q0 + r0 + i) * DMODEL + h * HDIM + c0) = out;
    }
}

// ---------------------------------------------------------------------------
extern "C" void kernel_launch(void* const* d_in, const int* in_sizes, int n_in,
                              void* d_out, int out_size)
{
    const float* q   = (const float*)d_in[0];
    const float* k   = (const float*)d_in[1];
    const float* v   = (const float*)d_in[2];
    const float* Wq  = (const float*)d_in[3];
    const float* bq  = (const float*)d_in[4];
    const float* Wk  = (const float*)d_in[5];
    const float* bk  = (const float*)d_in[6];
    const float* Wv  = (const float*)d_in[7];
    const float* bv  = (const float*)d_in[8];
    const float* Wo  = (const float*)d_in[9];
    const float* bo  = (const float*)d_in[10];
    const float* rp  = (const float*)d_in[11];
    float* out = (float*)d_out;

    float *dQ, *dK, *dV, *dA;
    cudaGetSymbolAddress((void**)&dQ, g_Q);
    cudaGetSymbolAddress((void**)&dK, g_K);
    cudaGetSymbolAddress((void**)&dV, g_V);
    cudaGetSymbolAddress((void**)&dA, g_A);

    cudaFuncSetAttribute(attn_kernel, cudaFuncAttributeMaxDynamicSharedMemorySize,
                         (int)ATTN_SMEM);

    dim3 gblk(256);
    dim3 ggrid(DMODEL / 64, MROWS / 64);   // (8, 128)

    gemm_xwt<<<ggrid, gblk>>>(q, Wq, bq, dQ);
    gemm_xwt<<<ggrid, gblk>>>(k, Wk, bk, dK);
    gemm_xwt<<<ggrid, gblk>>>(v, Wv, bv, dV);

    dim3 agrid(SEQ / 64, NHEAD, BATCH);    // (64, 8, 2)
    attn_kernel<<<agrid, gblk, ATTN_SMEM>>>(dQ, dK, dV, rp, dA);

    gemm_xwt<<<ggrid, gblk>>>(dA, Wo, bo, out);
}

// round 2
// speedup vs baseline: 1.2689x; 1.2689x over previous
#include <cuda_runtime.h>
#include <cuda_bf16.h>
#include <math.h>

#define BATCH 2
#define SEQ   4096
#define DMODEL 512
#define NHEAD 8
#define HDIM  64
#define MROWS (BATCH*SEQ)
#define MAXREL 2

typedef unsigned long long ull;

// Scratch (device globals — no runtime allocation allowed)
__device__ float g_Q[MROWS * DMODEL];
__device__ float g_K[MROWS * DMODEL];
__device__ float g_V[MROWS * DMODEL];
__device__ float g_A[MROWS * DMODEL];

// ---------------- packed f32x2 helpers ----------------
__device__ __forceinline__ ull pk2(float x, float y) {
    ull r;
    asm("mov.b64 %0, {%1, %2};" : "=l"(r) : "f"(x), "f"(y));
    return r;
}
__device__ __forceinline__ void fma2(ull& d, ull a, ull b) {
    asm("fma.rn.f32x2 %0, %1, %2, %0;" : "+l"(d) : "l"(a), "l"(b));
}
__device__ __forceinline__ float2 upk(ull v) {
    float2 f;
    asm("mov.b64 {%0, %1}, %2;" : "=f"(f.x), "=f"(f.y) : "l"(v));
    return f;
}

// ---------------------------------------------------------------------------
// GEMM: C[M,512] = X[M,512] @ W^T + bias.  128x128 tile, BK=16, 256 thr, 8x8.
// ---------------------------------------------------------------------------
__global__ __launch_bounds__(256, 2) void gemm_xwt(const float* __restrict__ X,
                                                   const float* __restrict__ W,
                                                   const float* __restrict__ bias,
                                                   float* __restrict__ C)
{
    __shared__ float As[16 * 132];   // [k][m]
    __shared__ float Bs[16 * 132];   // [k][n]

    const int tid = threadIdx.x;
    const int ty = tid >> 4, tx = tid & 15;
    const int r0 = ty * 8, c0 = tx * 8;
    const int m0 = blockIdx.y * 128, n0 = blockIdx.x * 128;

    const int lr = tid >> 1;          // 0..127
    const int lk = (tid & 1) * 8;     // 0 or 8

    const float* Xg = X + (size_t)(m0 + lr) * DMODEL + lk;
    const float* Wg = W + (size_t)(n0 + lr) * DMODEL + lk;

    ull acc[8][4];
#pragma unroll
    for (int i = 0; i < 8; i++)
#pragma unroll
        for (int jp = 0; jp < 4; jp++) acc[i][jp] = 0ull;

    for (int k0 = 0; k0 < DMODEL; k0 += 16) {
        const float4 x0 = *(const float4*)(Xg + k0);
        const float4 x1 = *(const float4*)(Xg + k0 + 4);
        const float4 w0 = *(const float4*)(Wg + k0);
        const float4 w1 = *(const float4*)(Wg + k0 + 4);
        __syncthreads();
        As[(lk + 0) * 132 + lr] = x0.x; As[(lk + 1) * 132 + lr] = x0.y;
        As[(lk + 2) * 132 + lr] = x0.z; As[(lk + 3) * 132 + lr] = x0.w;
        As[(lk + 4) * 132 + lr] = x1.x; As[(lk + 5) * 132 + lr] = x1.y;
        As[(lk + 6) * 132 + lr] = x1.z; As[(lk + 7) * 132 + lr] = x1.w;
        Bs[(lk + 0) * 132 + lr] = w0.x; Bs[(lk + 1) * 132 + lr] = w0.y;
        Bs[(lk + 2) * 132 + lr] = w0.z; Bs[(lk + 3) * 132 + lr] = w0.w;
        Bs[(lk + 4) * 132 + lr] = w1.x; Bs[(lk + 5) * 132 + lr] = w1.y;
        Bs[(lk + 6) * 132 + lr] = w1.z; Bs[(lk + 7) * 132 + lr] = w1.w;
        __syncthreads();
#pragma unroll
        for (int kk = 0; kk < 16; kk++) {
            const float4 a0 = *(const float4*)&As[kk * 132 + r0];
            const float4 a1 = *(const float4*)&As[kk * 132 + r0 + 4];
            const ulonglong2 b0 = *(const ulonglong2*)&Bs[kk * 132 + c0];
            const ulonglong2 b1 = *(const ulonglong2*)&Bs[kk * 132 + c0 + 4];
            ull aa;
            aa = pk2(a0.x, a0.x); fma2(acc[0][0], aa, b0.x); fma2(acc[0][1], aa, b0.y); fma2(acc[0][2], aa, b1.x); fma2(acc[0][3], aa, b1.y);
            aa = pk2(a0.y, a0.y); fma2(acc[1][0], aa, b0.x); fma2(acc[1][1], aa, b0.y); fma2(acc[1][2], aa, b1.x); fma2(acc[1][3], aa, b1.y);
            aa = pk2(a0.z, a0.z); fma2(acc[2][0], aa, b0.x); fma2(acc[2][1], aa, b0.y); fma2(acc[2][2], aa, b1.x); fma2(acc[2][3], aa, b1.y);
            aa = pk2(a0.w, a0.w); fma2(acc[3][0], aa, b0.x); fma2(acc[3][1], aa, b0.y); fma2(acc[3][2], aa, b1.x); fma2(acc[3][3], aa, b1.y);
            aa = pk2(a1.x, a1.x); fma2(acc[4][0], aa, b0.x); fma2(acc[4][1], aa, b0.y); fma2(acc[4][2], aa, b1.x); fma2(acc[4][3], aa, b1.y);
            aa = pk2(a1.y, a1.y); fma2(acc[5][0], aa, b0.x); fma2(acc[5][1], aa, b0.y); fma2(acc[5][2], aa, b1.x); fma2(acc[5][3], aa, b1.y);
            aa = pk2(a1.z, a1.z); fma2(acc[6][0], aa, b0.x); fma2(acc[6][1], aa, b0.y); fma2(acc[6][2], aa, b1.x); fma2(acc[6][3], aa, b1.y);
            aa = pk2(a1.w, a1.w); fma2(acc[7][0], aa, b0.x); fma2(acc[7][1], aa, b0.y); fma2(acc[7][2], aa, b1.x); fma2(acc[7][3], aa, b1.y);
        }
    }

    const float4 bv0 = *(const float4*)(bias + n0 + c0);
    const float4 bv1 = *(const float4*)(bias + n0 + c0 + 4);
#pragma unroll
    for (int i = 0; i < 8; i++) {
        float2 g0 = upk(acc[i][0]), g1 = upk(acc[i][1]);
        float2 g2 = upk(acc[i][2]), g3 = upk(acc[i][3]);
        float4 oA = make_float4(g0.x + bv0.x, g0.y + bv0.y, g1.x + bv0.z, g1.y + bv0.w);
        float4 oB = make_float4(g2.x + bv1.x, g2.y + bv1.y, g3.x + bv1.z, g3.y + bv1.w);
        float* Cp = C + (size_t)(m0 + r0 + i) * DMODEL + n0 + c0;
        *(float4*)Cp = oA;
        *(float4*)(Cp + 4) = oB;
    }
}

// ---------------------------------------------------------------------------
// Attention: 128 query x 128 key tiles, no-max softmax (range-safe), FFMA2.
// Smem: Qs/Ks transposed [hd][row] pitch 132; Vs [key][68]; Ps [key][128]
// with XOR swizzle on 16B row-blocks (kills the 16-way store conflict).
// ---------------------------------------------------------------------------
#define ATTN_SMEM ((64*132 + 64*132 + 128*68 + 128*128 + 8) * sizeof(float))

__global__ __launch_bounds__(256, 1) void attn_kernel(const float* __restrict__ Q,
                                                      const float* __restrict__ K,
                                                      const float* __restrict__ V,
                                                      const float* __restrict__ relpos,
                                                      float* __restrict__ Out)
{
    extern __shared__ float sm[];
    float* Qs = sm;                     // [64][132]
    float* Ks = Qs + 64 * 132;          // [64][132]
    float* Vs = Ks + 64 * 132;          // [128][68]
    float* Ps = Vs + 128 * 68;          // [128][128] swizzled
    float* rbs = Ps + 128 * 128;        // [8]

    const int tid = threadIdx.x;
    const int ty = tid >> 4, tx = tid & 15;
    const int r0 = ty * 8;              // query rows (local)
    const int ck0 = tx * 8;             // key cols (local, QK phase)
    const int cv0 = tx * 4;             // hd cols (PV phase)
    const int b = blockIdx.z, h = blockIdx.y;
    const int q0 = blockIdx.x * 128;

    const int lkey = tid >> 1;          // 0..127
    const int lh0 = (tid & 1) * 32;     // 0 or 32

    if (tid < 5) rbs[tid] = relpos[h * 5 + tid];

    // Q tile -> Qs transposed, pre-scaled by 1/sqrt(64)
    {
        const float* Qg = Q + (size_t)(b * SEQ + q0 + lkey) * DMODEL + h * HDIM + lh0;
#pragma unroll
        for (int ii = 0; ii < 4; ii++) {
            float4 x0 = *(const float4*)(Qg + ii * 8);
            float4 x1 = *(const float4*)(Qg + ii * 8 + 4);
            const int d = lh0 + ii * 8;
            Qs[(d + 0) * 132 + lkey] = x0.x * 0.125f;
            Qs[(d + 1) * 132 + lkey] = x0.y * 0.125f;
            Qs[(d + 2) * 132 + lkey] = x0.z * 0.125f;
            Qs[(d + 3) * 132 + lkey] = x0.w * 0.125f;
            Qs[(d + 4) * 132 + lkey] = x1.x * 0.125f;
            Qs[(d + 5) * 132 + lkey] = x1.y * 0.125f;
            Qs[(d + 6) * 132 + lkey] = x1.z * 0.125f;
            Qs[(d + 7) * 132 + lkey] = x1.w * 0.125f;
        }
    }

    ull o[4][4];                        // [row-pair][hd]
#pragma unroll
    for (int i = 0; i < 4; i++)
#pragma unroll
        for (int j = 0; j < 4; j++) o[i][j] = 0ull;
    float ls[8];
#pragma unroll
    for (int i = 0; i < 8; i++) ls[i] = 0.f;

    const int pb0 = ty * 2;             // 16B row-block of r0

    for (int kt = 0; kt < SEQ / 128; kt++) {
        const int k0 = kt * 128;
        __syncthreads();                // prev PV done with Ks/Vs/Ps

        // K tile -> Ks transposed
        {
            const float* Kg = K + (size_t)(b * SEQ + k0 + lkey) * DMODEL + h * HDIM + lh0;
#pragma unroll
            for (int ii = 0; ii < 4; ii++) {
                float4 x0 = *(const float4*)(Kg + ii * 8);
                float4 x1 = *(const float4*)(Kg + ii * 8 + 4);
                const int d = lh0 + ii * 8;
                Ks[(d + 0) * 132 + lkey] = x0.x;
                Ks[(d + 1) * 132 + lkey] = x0.y;
                Ks[(d + 2) * 132 + lkey] = x0.z;
                Ks[(d + 3) * 132 + lkey] = x0.w;
                Ks[(d + 4) * 132 + lkey] = x1.x;
                Ks[(d + 5) * 132 + lkey] = x1.y;
                Ks[(d + 6) * 132 + lkey] = x1.z;
                Ks[(d + 7) * 132 + lkey] = x1.w;
            }
        }
        // V tile -> Vs row-major
        {
            const float* Vg = V + (size_t)(b * SEQ + k0) * DMODEL + h * HDIM;
#pragma unroll
            for (int ii = 0; ii < 8; ii++) {
                const int idx = tid + ii * 256;
                const int key = idx >> 4;
                const int hd = (idx & 15) * 4;
                float4 vv = *(const float4*)(Vg + (size_t)key * DMODEL + hd);
                *(float4*)&Vs[key * 68 + hd] = vv;
            }
        }
        __syncthreads();

        // ---- S = (Q/8) @ K^T ----
        ull s[8][4];
#pragma unroll
        for (int i = 0; i < 8; i++)
#pragma unroll
            for (int jp = 0; jp < 4; jp++) s[i][jp] = 0ull;
#pragma unroll 4
        for (int d = 0; d < 64; d++) {
            const float4 a0 = *(const float4*)&Qs[d * 132 + r0];
            const float4 a1 = *(const float4*)&Qs[d * 132 + r0 + 4];
            const ulonglong2 b0 = *(const ulonglong2*)&Ks[d * 132 + ck0];
            const ulonglong2 b1 = *(const ulonglong2*)&Ks[d * 132 + ck0 + 4];
            ull aa;
            aa = pk2(a0.x, a0.x); fma2(s[0][0], aa, b0.x); fma2(s[0][1], aa, b0.y); fma2(s[0][2], aa, b1.x); fma2(s[0][3], aa, b1.y);
            aa = pk2(a0.y, a0.y); fma2(s[1][0], aa, b0.x); fma2(s[1][1], aa, b0.y); fma2(s[1][2], aa, b1.x); fma2(s[1][3], aa, b1.y);
            aa = pk2(a0.z, a0.z); fma2(s[2][0], aa, b0.x); fma2(s[2][1], aa, b0.y); fma2(s[2][2], aa, b1.x); fma2(s[2][3], aa, b1.y);
            aa = pk2(a0.w, a0.w); fma2(s[3][0], aa, b0.x); fma2(s[3][1], aa, b0.y); fma2(s[3][2], aa, b1.x); fma2(s[3][3], aa, b1.y);
            aa = pk2(a1.x, a1.x); fma2(s[4][0], aa, b0.x); fma2(s[4][1], aa, b0.y); fma2(s[4][2], aa, b1.x); fma2(s[4][3], aa, b1.y);
            aa = pk2(a1.y, a1.y); fma2(s[5][0], aa, b0.x); fma2(s[5][1], aa, b0.y); fma2(s[5][2], aa, b1.x); fma2(s[5][3], aa, b1.y);
            aa = pk2(a1.z, a1.z); fma2(s[6][0], aa, b0.x); fma2(s[6][1], aa, b0.y); fma2(s[6][2], aa, b1.x); fma2(s[6][3], aa, b1.y);
            aa = pk2(a1.w, a1.w); fma2(s[7][0], aa, b0.x); fma2(s[7][1], aa, b0.y); fma2(s[7][2], aa, b1.x); fma2(s[7][3], aa, b1.y);
        }

        // ---- bias + exp (no max subtraction; range-safe) + rowsum ----
        float p[8][8];
        const int dmin = k0 - q0 - 127;
        const int dmax = k0 + 127 - q0;
        if (dmin > MAXREL || dmax < -MAXREL) {
            const float bb = (dmin > MAXREL) ? rbs[4] : rbs[0];
#pragma unroll
            for (int i = 0; i < 8; i++)
#pragma unroll
                for (int jp = 0; jp < 4; jp++) {
                    float2 f = upk(s[i][jp]);
                    p[i][2 * jp]     = __expf(f.x + bb);
                    p[i][2 * jp + 1] = __expf(f.y + bb);
                }
        } else {
#pragma unroll
            for (int i = 0; i < 8; i++) {
                const int qi = q0 + r0 + i;
#pragma unroll
                for (int jp = 0; jp < 4; jp++) {
                    float2 f = upk(s[i][jp]);
                    const int rel0 = (k0 + ck0 + 2 * jp) - qi;
                    const int i0 = min(max(rel0, -MAXREL), MAXREL) + MAXREL;
                    const int i1 = min(max(rel0 + 1, -MAXREL), MAXREL) + MAXREL;
                    p[i][2 * jp]     = __expf(f.x + rbs[i0]);
                    p[i][2 * jp + 1] = __expf(f.y + rbs[i1]);
                }
            }
        }
#pragma unroll
        for (int i = 0; i < 8; i++)
            ls[i] += ((p[i][0] + p[i][1]) + (p[i][2] + p[i][3])) +
                     ((p[i][4] + p[i][5]) + (p[i][6] + p[i][7]));

        // ---- P -> Ps [key][row], XOR-swizzled 16B blocks ----
#pragma unroll
        for (int j = 0; j < 8; j++) {
            const int key = ck0 + j;
            const int xr = (key >> 3) & 7;
            float4 lo = make_float4(p[0][j], p[1][j], p[2][j], p[3][j]);
            float4 hi = make_float4(p[4][j], p[5][j], p[6][j], p[7][j]);
            *(float4*)&Ps[key * 128 + ((pb0 ^ xr) << 2)]       = lo;
            *(float4*)&Ps[key * 128 + (((pb0 + 1) ^ xr) << 2)] = hi;
        }
        __syncthreads();

        // ---- O += P @ V ----
#pragma unroll 4
        for (int kk = 0; kk < 128; kk++) {
            const int xr = (kk >> 3) & 7;
            const ulonglong2 pA = *(const ulonglong2*)&Ps[kk * 128 + ((pb0 ^ xr) << 2)];
            const ulonglong2 pB = *(const ulonglong2*)&Ps[kk * 128 + (((pb0 + 1) ^ xr) << 2)];
            const float4 v4 = *(const float4*)&Vs[kk * 68 + cv0];
            const ull v0 = pk2(v4.x, v4.x);
            const ull v1 = pk2(v4.y, v4.y);
            const ull v2 = pk2(v4.z, v4.z);
            const ull v3 = pk2(v4.w, v4.w);
            fma2(o[0][0], pA.x, v0); fma2(o[0][1], pA.x, v1); fma2(o[0][2], pA.x, v2); fma2(o[0][3], pA.x, v3);
            fma2(o[1][0], pA.y, v0); fma2(o[1][1], pA.y, v1); fma2(o[1][2], pA.y, v2); fma2(o[1][3], pA.y, v3);
            fma2(o[2][0], pB.x, v0); fma2(o[2][1], pB.x, v1); fma2(o[2][2], pB.x, v2); fma2(o[2][3], pB.x, v3);
            fma2(o[3][0], pB.y, v0); fma2(o[3][1], pB.y, v1); fma2(o[3][2], pB.y, v2); fma2(o[3][3], pB.y, v3);
        }
    }

    // ---- rowsum reduce across the 16 tx lanes (within warp halves) ----
#pragma unroll
    for (int i = 0; i < 8; i++) {
        ls[i] += __shfl_xor_sync(0xFFFFFFFFu, ls[i], 1);
        ls[i] += __shfl_xor_sync(0xFFFFFFFFu, ls[i], 2);
        ls[i] += __shfl_xor_sync(0xFFFFFFFFu, ls[i], 4);
        ls[i] += __shfl_xor_sync(0xFFFFFFFFu, ls[i], 8);
    }

    // ---- normalize + store ----
#pragma unroll
    for (int pr = 0; pr < 4; pr++) {
        float2 f0 = upk(o[pr][0]), f1 = upk(o[pr][1]);
        float2 f2 = upk(o[pr][2]), f3 = upk(o[pr][3]);
        const float inv0 = 1.0f / ls[2 * pr];
        const float inv1 = 1.0f / ls[2 * pr + 1];
        float4 oA = make_float4(f0.x * inv0, f1.x * inv0, f2.x * inv0, f3.x * inv0);
        float4 oB = make_float4(f0.y * inv1, f1.y * inv1, f2.y * inv1, f3.y * inv1);
        const size_t base = (size_t)(b * SEQ + q0 + r0 + 2 * pr) * DMODEL + h * HDIM + cv0;
        *(float4*)(Out + base) = oA;
        *(float4*)(Out + base + DMODEL) = oB;
    }
}

// ---------------------------------------------------------------------------
extern "C" void kernel_launch(void* const* d_in, const int* in_sizes, int n_in,
                              void* d_out, int out_size)
{
    const float* q  = (const float*)d_in[0];
    const float* k  = (const float*)d_in[1];
    const float* v  = (const float*)d_in[2];
    const float* Wq = (const float*)d_in[3];
    const float* bq = (const float*)d_in[4];
    const float* Wk = (const float*)d_in[5];
    const float* bk = (const float*)d_in[6];
    const float* Wv = (const float*)d_in[7];
    const float* bv = (const float*)d_in[8];
    const float* Wo = (const float*)d_in[9];
    const float* bo = (const float*)d_in[10];
    const float* rp = (const float*)d_in[11];
    float* out = (float*)d_out;

    float *dQ, *dK, *dV, *dA;
    cudaGetSymbolAddress((void**)&dQ, g_Q);
    cudaGetSymbolAddress((void**)&dK, g_K);
    cudaGetSymbolAddress((void**)&dV, g_V);
    cudaGetSymbolAddress((void**)&dA, g_A);

    cudaFuncSetAttribute(attn_kernel, cudaFuncAttributeMaxDynamicSharedMemorySize,
                         (int)ATTN_SMEM);

    dim3 gblk(256);
    dim3 ggrid(DMODEL / 128, MROWS / 128);   // (4, 64)

    gemm_xwt<<<ggrid, gblk>>>(q, Wq, bq, dQ);
    gemm_xwt<<<ggrid, gblk>>>(k, Wk, bk, dK);
    gemm_xwt<<<ggrid, gblk>>>(v, Wv, bv, dV);

    dim3 agrid(SEQ / 128, NHEAD, BATCH);     // (32, 8, 2)
    attn_kernel<<<agrid, gblk, ATTN_SMEM>>>(dQ, dK, dV, rp, dA);

    gemm_xwt<<<ggrid, gblk>>>(dA, Wo, bo, out);
}

// round 5
// speedup vs baseline: 2.3237x; 1.8312x over previous
#include <cuda_runtime.h>
#include <cuda_bf16.h>
#include <math.h>
#include <stdint.h>

#define BATCH 2
#define SEQ   4096
#define DMODEL 512
#define NHEAD 8
#define HDIM  64
#define MROWS (BATCH*SEQ)
#define MAXREL 2

typedef unsigned long long ull;

// fp32 scratch
__device__ float g_Q[MROWS * DMODEL];
__device__ float g_K[MROWS * DMODEL];
__device__ float g_V[MROWS * DMODEL];
__device__ float g_A[MROWS * DMODEL];
// bf16 hi/lo split scratch
__device__ unsigned short g_Qh[MROWS * DMODEL];
__device__ unsigned short g_Ql[MROWS * DMODEL];
__device__ unsigned short g_Kh[MROWS * DMODEL];
__device__ unsigned short g_Kl[MROWS * DMODEL];
__device__ unsigned short g_Vh[MROWS * DMODEL];
__device__ unsigned short g_Vl[MROWS * DMODEL];

// ---------------- packed f32x2 helpers (GEMM) ----------------
__device__ __forceinline__ ull pk2(float x, float y) {
    ull r; asm("mov.b64 %0, {%1, %2};" : "=l"(r) : "f"(x), "f"(y)); return r;
}
__device__ __forceinline__ void fma2(ull& d, ull a, ull b) {
    asm("fma.rn.f32x2 %0, %1, %2, %0;" : "+l"(d) : "l"(a), "l"(b));
}
__device__ __forceinline__ float2 upk(ull v) {
    float2 f; asm("mov.b64 {%0, %1}, %2;" : "=f"(f.x), "=f"(f.y) : "l"(v)); return f;
}

// split (a,b) into bf16 hi-pair + lo-pair words: h = {lo=bf16(a), hi=bf16(b)}
__device__ __forceinline__ void split2(float a, float b, uint32_t& h, uint32_t& l) {
    asm("cvt.rn.bf16x2.f32 %0, %1, %2;" : "=r"(h) : "f"(b), "f"(a));
    float ha = __uint_as_float(h << 16);
    float hb = __uint_as_float(h & 0xffff0000u);
    float ra = a - ha, rb = b - hb;
    asm("cvt.rn.bf16x2.f32 %0, %1, %2;" : "=r"(l) : "f"(rb), "f"(ra));
}

// ---------------------------------------------------------------------------
// GEMM (unchanged, proven): C[M,512] = X @ W^T + bias, FFMA2 128x128 tiles
// ---------------------------------------------------------------------------
__global__ __launch_bounds__(256, 2) void gemm_xwt(const float* __restrict__ X,
                                                   const float* __restrict__ W,
                                                   const float* __restrict__ bias,
                                                   float* __restrict__ C)
{
    __shared__ float As[16 * 132];
    __shared__ float Bs[16 * 132];

    const int tid = threadIdx.x;
    const int ty = tid >> 4, tx = tid & 15;
    const int r0 = ty * 8, c0 = tx * 8;
    const int m0 = blockIdx.y * 128, n0 = blockIdx.x * 128;
    const int lr = tid >> 1;
    const int lk = (tid & 1) * 8;

    const float* Xg = X + (size_t)(m0 + lr) * DMODEL + lk;
    const float* Wg = W + (size_t)(n0 + lr) * DMODEL + lk;

    ull acc[8][4];
#pragma unroll
    for (int i = 0; i < 8; i++)
#pragma unroll
        for (int jp = 0; jp < 4; jp++) acc[i][jp] = 0ull;

    for (int k0 = 0; k0 < DMODEL; k0 += 16) {
        const float4 x0 = *(const float4*)(Xg + k0);
        const float4 x1 = *(const float4*)(Xg + k0 + 4);
        const float4 w0 = *(const float4*)(Wg + k0);
        const float4 w1 = *(const float4*)(Wg + k0 + 4);
        __syncthreads();
        As[(lk + 0) * 132 + lr] = x0.x; As[(lk + 1) * 132 + lr] = x0.y;
        As[(lk + 2) * 132 + lr] = x0.z; As[(lk + 3) * 132 + lr] = x0.w;
        As[(lk + 4) * 132 + lr] = x1.x; As[(lk + 5) * 132 + lr] = x1.y;
        As[(lk + 6) * 132 + lr] = x1.z; As[(lk + 7) * 132 + lr] = x1.w;
        Bs[(lk + 0) * 132 + lr] = w0.x; Bs[(lk + 1) * 132 + lr] = w0.y;
        Bs[(lk + 2) * 132 + lr] = w0.z; Bs[(lk + 3) * 132 + lr] = w0.w;
        Bs[(lk + 4) * 132 + lr] = w1.x; Bs[(lk + 5) * 132 + lr] = w1.y;
        Bs[(lk + 6) * 132 + lr] = w1.z; Bs[(lk + 7) * 132 + lr] = w1.w;
        __syncthreads();
#pragma unroll
        for (int kk = 0; kk < 16; kk++) {
            const float4 a0 = *(const float4*)&As[kk * 132 + r0];
            const float4 a1 = *(const float4*)&As[kk * 132 + r0 + 4];
            const ulonglong2 b0 = *(const ulonglong2*)&Bs[kk * 132 + c0];
            const ulonglong2 b1 = *(const ulonglong2*)&Bs[kk * 132 + c0 + 4];
            ull aa;
            aa = pk2(a0.x, a0.x); fma2(acc[0][0], aa, b0.x); fma2(acc[0][1], aa, b0.y); fma2(acc[0][2], aa, b1.x); fma2(acc[0][3], aa, b1.y);
            aa = pk2(a0.y, a0.y); fma2(acc[1][0], aa, b0.x); fma2(acc[1][1], aa, b0.y); fma2(acc[1][2], aa, b1.x); fma2(acc[1][3], aa, b1.y);
            aa = pk2(a0.z, a0.z); fma2(acc[2][0], aa, b0.x); fma2(acc[2][1], aa, b0.y); fma2(acc[2][2], aa, b1.x); fma2(acc[2][3], aa, b1.y);
            aa = pk2(a0.w, a0.w); fma2(acc[3][0], aa, b0.x); fma2(acc[3][1], aa, b0.y); fma2(acc[3][2], aa, b1.x); fma2(acc[3][3], aa, b1.y);
            aa = pk2(a1.x, a1.x); fma2(acc[4][0], aa, b0.x); fma2(acc[4][1], aa, b0.y); fma2(acc[4][2], aa, b1.x); fma2(acc[4][3], aa, b1.y);
            aa = pk2(a1.y, a1.y); fma2(acc[5][0], aa, b0.x); fma2(acc[5][1], aa, b0.y); fma2(acc[5][2], aa, b1.x); fma2(acc[5][3], aa, b1.y);
            aa = pk2(a1.z, a1.z); fma2(acc[6][0], aa, b0.x); fma2(acc[6][1], aa, b0.y); fma2(acc[6][2], aa, b1.x); fma2(acc[6][3], aa, b1.y);
            aa = pk2(a1.w, a1.w); fma2(acc[7][0], aa, b0.x); fma2(acc[7][1], aa, b0.y); fma2(acc[7][2], aa, b1.x); fma2(acc[7][3], aa, b1.y);
        }
    }

    const float4 bv0 = *(const float4*)(bias + n0 + c0);
    const float4 bv1 = *(const float4*)(bias + n0 + c0 + 4);
#pragma unroll
    for (int i = 0; i < 8; i++) {
        float2 g0 = upk(acc[i][0]), g1 = upk(acc[i][1]);
        float2 g2 = upk(acc[i][2]), g3 = upk(acc[i][3]);
        float4 oA = make_float4(g0.x + bv0.x, g0.y + bv0.y, g1.x + bv0.z, g1.y + bv0.w);
        float4 oB = make_float4(g2.x + bv1.x, g2.y + bv1.y, g3.x + bv1.z, g3.y + bv1.w);
        float* Cp = C + (size_t)(m0 + r0 + i) * DMODEL + n0 + c0;
        *(float4*)Cp = oA;
        *(float4*)(Cp + 4) = oB;
    }
}

// ---------------------------------------------------------------------------
// Split Q(K,V) fp32 -> bf16 hi/lo arrays. Q pre-scaled by 1/sqrt(64).
// ---------------------------------------------------------------------------
__global__ __launch_bounds__(256) void split_qkv()
{
    const size_t i = (size_t)blockIdx.x * 256 + threadIdx.x;   // float4 index
    float4 q = ((const float4*)g_Q)[i];
    float4 k = ((const float4*)g_K)[i];
    float4 v = ((const float4*)g_V)[i];
    uint2 h, l;
    split2(q.x * 0.125f, q.y * 0.125f, h.x, l.x);
    split2(q.z * 0.125f, q.w * 0.125f, h.y, l.y);
    ((uint2*)g_Qh)[i] = h; ((uint2*)g_Ql)[i] = l;
    split2(k.x, k.y, h.x, l.x);
    split2(k.z, k.w, h.y, l.y);
    ((uint2*)g_Kh)[i] = h; ((uint2*)g_Kl)[i] = l;
    split2(v.x, v.y, h.x, l.x);
    split2(v.z, v.w, h.y, l.y);
    ((uint2*)g_Vh)[i] = h; ((uint2*)g_Vl)[i] = l;
}

// ===========================================================================
// mma.sync attention
// ===========================================================================

#define SW128(o) ((o) ^ (((o) >> 3) & 0x70))

// smem byte offsets: Qhi 16K, Qlo 16K, then 2 stages of {Kh,Kl,Vh,Vl} 16K each
#define OQH 0
#define OQL 16384
#define OST 32768
#define STAGE_SZ 65536
#define SKH 0
#define SKL 16384
#define SVH 32768
#define SVL 49152
#define ATTN_SMEM (OST + 2 * STAGE_SZ)

static __device__ __forceinline__ uint32_t smem_u32(const void* p) {
    uint32_t a;
    asm("{ .reg .u64 t; cvta.to.shared.u64 t, %1; cvt.u32.u64 %0, t; }" : "=r"(a) : "l"(p));
    return a;
}
__device__ __forceinline__ void ldsm4(uint32_t* r, uint32_t addr) {
    asm volatile("ldmatrix.sync.aligned.m8n8.x4.shared.b16 {%0,%1,%2,%3}, [%4];"
                 : "=r"(r[0]), "=r"(r[1]), "=r"(r[2]), "=r"(r[3]) : "r"(addr));
}
__device__ __forceinline__ void ldsm4t(uint32_t* r, uint32_t addr) {
    asm volatile("ldmatrix.sync.aligned.m8n8.x4.trans.shared.b16 {%0,%1,%2,%3}, [%4];"
                 : "=r"(r[0]), "=r"(r[1]), "=r"(r[2]), "=r"(r[3]) : "r"(addr));
}
__device__ __forceinline__ void mmabf16(float* c, const uint32_t* a, uint32_t b0, uint32_t b1) {
    asm volatile("mma.sync.aligned.m16n8k16.row.col.f32.bf16.bf16.f32 "
                 "{%0,%1,%2,%3}, {%4,%5,%6,%7}, {%8,%9}, {%0,%1,%2,%3};"
                 : "+f"(c[0]), "+f"(c[1]), "+f"(c[2]), "+f"(c[3])
                 : "r"(a[0]), "r"(a[1]), "r"(a[2]), "r"(a[3]), "r"(b0), "r"(b1));
}
__device__ __forceinline__ void cpa16(uint32_t d, const void* s) {
    asm volatile("cp.async.cg.shared.global [%0], [%1], 16;" :: "r"(d), "l"(s));
}
#define CP_COMMIT() asm volatile("cp.async.commit_group;" ::: "memory")
#define CP_WAIT1()  asm volatile("cp.async.wait_group 1;" ::: "memory")

__global__ __launch_bounds__(256) void attn_kernel(
    const unsigned short* __restrict__ Qh, const unsigned short* __restrict__ Ql,
    const unsigned short* __restrict__ Kh, const unsigned short* __restrict__ Kl,
    const unsigned short* __restrict__ Vh, const unsigned short* __restrict__ Vl,
    const float* __restrict__ relpos, float* __restrict__ Out)
{
    extern __shared__ char smp[];
    const uint32_t sb = smem_u32(smp);

    const int tid = threadIdx.x;
    const int w = tid >> 5;
    const int lane = tid & 31;
    const int b = blockIdx.z, h = blockIdx.y;
    const int q0 = blockIdx.x * 128;

    const float rb0 = relpos[h * 5 + 0];
    const float rb1 = relpos[h * 5 + 1];
    const float rb2 = relpos[h * 5 + 2];
    const float rb3 = relpos[h * 5 + 3];
    const float rb4 = relpos[h * 5 + 4];

    // ---- load Q tile (bf16 hi/lo) into smem with SW128 ----
    {
        const int row = tid >> 1;                 // 0..127
        const int ch0 = (tid & 1) * 4;            // 16B chunk base (of 8)
        const size_t gb = (size_t)(b * SEQ + q0 + row) * DMODEL + h * HDIM + ch0 * 8;
#pragma unroll
        for (int ci = 0; ci < 4; ci++) {
            const uint32_t off = SW128((uint32_t)(row * 128 + (ch0 + ci) * 16));
            *(uint4*)(smp + OQH + off) = *(const uint4*)(Qh + gb + ci * 8);
            *(uint4*)(smp + OQL + off) = *(const uint4*)(Ql + gb + ci * 8);
        }
    }

    // cp.async K/V tile loader
    const int krow = tid >> 1;
    const int kch0 = (tid & 1) * 4;
    const size_t kgb0 = (size_t)(b * SEQ + krow) * DMODEL + h * HDIM + kch0 * 8;

    // prologue: stage 0
    {
        const uint32_t st = sb + OST;
        const size_t gb = kgb0;  // k0 = 0
#pragma unroll
        for (int ci = 0; ci < 4; ci++) {
            const uint32_t off = SW128((uint32_t)(krow * 128 + (kch0 + ci) * 16));
            cpa16(st + SKH + off, Kh + gb + ci * 8);
            cpa16(st + SKL + off, Kl + gb + ci * 8);
            cpa16(st + SVH + off, Vh + gb + ci * 8);
            cpa16(st + SVL + off, Vl + gb + ci * 8);
        }
    }
    CP_COMMIT();

    // ldmatrix address bases (byte offsets before swizzle)
    const uint32_t base_qa = (uint32_t)((16 * w + (lane & 15)) * 128 + 16 * (lane >> 4));
    const uint32_t base_kb = (uint32_t)(((lane & 7) + ((lane & 16) >> 1)) * 128 + ((lane >> 3) & 1) * 16);
    const uint32_t base_vb = (uint32_t)(((lane & 7) + (lane & 8)) * 128 + ((lane >> 4) & 1) * 16);

    float co[8][4];
#pragma unroll
    for (int i = 0; i < 8; i++)
#pragma unroll
        for (int j = 0; j < 4; j++) co[i][j] = 0.f;
    float sum0 = 0.f, sum1 = 0.f;

    const int r0g = q0 + 16 * w + (lane >> 2);    // global q row for c0/c1
    const int kcol_off = 2 * (lane & 3);

    for (int kt = 0; kt < SEQ / 128; kt++) {
        const int k0 = kt * 128;

        // issue next tile
        if (kt + 1 < SEQ / 128) {
            const uint32_t st = sb + OST + ((kt + 1) & 1) * STAGE_SZ;
            const size_t gb = kgb0 + (size_t)(k0 + 128) * DMODEL;
#pragma unroll
            for (int ci = 0; ci < 4; ci++) {
                const uint32_t off = SW128((uint32_t)(krow * 128 + (kch0 + ci) * 16));
                cpa16(st + SKH + off, Kh + gb + ci * 8);
                cpa16(st + SKL + off, Kl + gb + ci * 8);
                cpa16(st + SVH + off, Vh + gb + ci * 8);
                cpa16(st + SVL + off, Vl + gb + ci * 8);
            }
        }
        CP_COMMIT();
        CP_WAIT1();
        __syncthreads();

        const uint32_t st = sb + OST + (kt & 1) * STAGE_SZ;
        const uint32_t KHb = st + SKH, KLb = st + SKL;
        const uint32_t VHb = st + SVH, VLb = st + SVL;
        const uint32_t QHb = sb + OQH, QLb = sb + OQL;

        // ---- S = Q @ K^T (3-term bf16) ----
        float cs[16][4];
#pragma unroll
        for (int i = 0; i < 16; i++)
#pragma unroll
            for (int j = 0; j < 4; j++) cs[i][j] = 0.f;

#pragma unroll
        for (int c = 0; c < 4; c++) {
            uint32_t ah[4], al[4];
            ldsm4(ah, QHb + SW128(base_qa + 32 * c));
            ldsm4(al, QLb + SW128(base_qa + 32 * c));
#pragma unroll
            for (int j2 = 0; j2 < 8; j2++) {
                uint32_t bh[4], bl[4];
                const uint32_t off = SW128(base_kb + 2048u * j2 + 32u * c);
                ldsm4(bh, KHb + off);
                ldsm4(bl, KLb + off);
                mmabf16(cs[2 * j2], ah, bh[0], bh[1]);
                mmabf16(cs[2 * j2], ah, bl[0], bl[1]);
                mmabf16(cs[2 * j2], al, bh[0], bh[1]);
                mmabf16(cs[2 * j2 + 1], ah, bh[2], bh[3]);
                mmabf16(cs[2 * j2 + 1], ah, bl[2], bl[3]);
                mmabf16(cs[2 * j2 + 1], al, bh[2], bh[3]);
            }
        }

        // ---- bias + exp + rowsum ----
        const bool uni = (k0 - (q0 + 127) > MAXREL) || ((k0 + 127) - q0 < -MAXREL);
        if (uni) {
            const float ub = (k0 > q0) ? rb4 : rb0;
#pragma unroll
            for (int j = 0; j < 16; j++) {
                cs[j][0] = __expf(cs[j][0] + ub);
                cs[j][1] = __expf(cs[j][1] + ub);
                cs[j][2] = __expf(cs[j][2] + ub);
                cs[j][3] = __expf(cs[j][3] + ub);
            }
        } else {
#pragma unroll
            for (int j = 0; j < 16; j++) {
                const int kc = k0 + 8 * j + kcol_off;
#pragma unroll
                for (int i = 0; i < 4; i++) {
                    const int rel = (kc + (i & 1)) - (r0g + (i >> 1) * 8);
                    const float bb = rel <= -MAXREL ? rb0 :
                                     rel >= MAXREL ? rb4 :
                                     rel == -1 ? rb1 : (rel == 0 ? rb2 : rb3);
                    cs[j][i] = __expf(cs[j][i] + bb);
                }
            }
        }
#pragma unroll
        for (int j = 0; j < 16; j++) {
            sum0 += cs[j][0] + cs[j][1];
            sum1 += cs[j][2] + cs[j][3];
        }

        // ---- O += P @ V (3-term bf16, P from registers) ----
#pragma unroll
        for (int kc = 0; kc < 8; kc++) {
            uint32_t ph[4], pl[4];
            split2(cs[2 * kc][0], cs[2 * kc][1], ph[0], pl[0]);
            split2(cs[2 * kc][2], cs[2 * kc][3], ph[1], pl[1]);
            split2(cs[2 * kc + 1][0], cs[2 * kc + 1][1], ph[2], pl[2]);
            split2(cs[2 * kc + 1][2], cs[2 * kc + 1][3], ph[3], pl[3]);
#pragma unroll
            for (int jv = 0; jv < 4; jv++) {
                uint32_t vh[4], vl[4];
                const uint32_t off = SW128(base_vb + 2048u * kc + 32u * jv);
                ldsm4t(vh, VHb + off);
                ldsm4t(vl, VLb + off);
                mmabf16(co[2 * jv], ph, vh[0], vh[1]);
                mmabf16(co[2 * jv], ph, vl[0], vl[1]);
                mmabf16(co[2 * jv], pl, vh[0], vh[1]);
                mmabf16(co[2 * jv + 1], ph, vh[2], vh[3]);
                mmabf16(co[2 * jv + 1], ph, vl[2], vl[3]);
                mmabf16(co[2 * jv + 1], pl, vh[2], vh[3]);
            }
        }
        __syncthreads();
    }

    // ---- rowsum reduce across the quad (lanes sharing t/4) ----
    sum0 += __shfl_xor_sync(0xFFFFFFFFu, sum0, 1);
    sum0 += __shfl_xor_sync(0xFFFFFFFFu, sum0, 2);
    sum1 += __shfl_xor_sync(0xFFFFFFFFu, sum1, 1);
    sum1 += __shfl_xor_sync(0xFFFFFFFFu, sum1, 2);
    const float inv0 = 1.0f / sum0;
    const float inv1 = 1.0f / sum1;

    // ---- store ----
    {
        float* O0 = Out + (size_t)(b * SEQ + r0g) * DMODEL + h * HDIM + kcol_off;
        float* O1 = O0 + 8 * DMODEL;
#pragma unroll
        for (int j = 0; j < 8; j++) {
            *(float2*)(O0 + 8 * j) = make_float2(co[j][0] * inv0, co[j][1] * inv0);
            *(float2*)(O1 + 8 * j) = make_float2(co[j][2] * inv1, co[j][3] * inv1);
        }
    }
}

// ---------------------------------------------------------------------------
extern "C" void kernel_launch(void* const* d_in, const int* in_sizes, int n_in,
                              void* d_out, int out_size)
{
    const float* q  = (const float*)d_in[0];
    const float* k  = (const float*)d_in[1];
    const float* v  = (const float*)d_in[2];
    const float* Wq = (const float*)d_in[3];
    const float* bq = (const float*)d_in[4];
    const float* Wk = (const float*)d_in[5];
    const float* bk = (const float*)d_in[6];
    const float* Wv = (const float*)d_in[7];
    const float* bv = (const float*)d_in[8];
    const float* Wo = (const float*)d_in[9];
    const float* bo = (const float*)d_in[10];
    const float* rp = (const float*)d_in[11];
    float* out = (float*)d_out;

    float *dQ, *dK, *dV, *dA;
    unsigned short *dQh, *dQl, *dKh, *dKl, *dVh, *dVl;
    cudaGetSymbolAddress((void**)&dQ, g_Q);
    cudaGetSymbolAddress((void**)&dK, g_K);
    cudaGetSymbolAddress((void**)&dV, g_V);
    cudaGetSymbolAddress((void**)&dA, g_A);
    cudaGetSymbolAddress((void**)&dQh, g_Qh);
    cudaGetSymbolAddress((void**)&dQl, g_Ql);
    cudaGetSymbolAddress((void**)&dKh, g_Kh);
    cudaGetSymbolAddress((void**)&dKl, g_Kl);
    cudaGetSymbolAddress((void**)&dVh, g_Vh);
    cudaGetSymbolAddress((void**)&dVl, g_Vl);

    cudaFuncSetAttribute(attn_kernel, cudaFuncAttributeMaxDynamicSharedMemorySize,
                         ATTN_SMEM);

    dim3 gblk(256);
    dim3 ggrid(DMODEL / 128, MROWS / 128);   // (4, 64)

    gemm_xwt<<<ggrid, gblk>>>(q, Wq, bq, dQ);
    gemm_xwt<<<ggrid, gblk>>>(k, Wk, bk, dK);
    gemm_xwt<<<ggrid, gblk>>>(v, Wv, bv, dV);

    split_qkv<<<MROWS * DMODEL / 4 / 256, 256>>>();

    dim3 agrid(SEQ / 128, NHEAD, BATCH);     // (32, 8, 2)
    attn_kernel<<<agrid, gblk, ATTN_SMEM>>>(dQh, dQl, dKh, dKl, dVh, dVl, rp, dA);

    gemm_xwt<<<ggrid, gblk>>>(dA, Wo, bo, out);
}

// round 6
// speedup vs baseline: 2.9005x; 1.2482x over previous
#include <cuda_runtime.h>
#include <cuda_bf16.h>
#include <math.h>
#include <stdint.h>

#define BATCH 2
#define SEQ   4096
#define DMODEL 512
#define NHEAD 8
#define HDIM  64
#define MROWS (BATCH*SEQ)
#define MAXREL 2

typedef unsigned long long ull;

// scratch
__device__ float g_A[MROWS * DMODEL];
__device__ unsigned short g_Qh[MROWS * DMODEL];
__device__ unsigned short g_Ql[MROWS * DMODEL];
__device__ unsigned short g_Kh[MROWS * DMODEL];
__device__ unsigned short g_Kl[MROWS * DMODEL];
__device__ unsigned short g_Vh[MROWS * DMODEL];
__device__ unsigned short g_Vl[MROWS * DMODEL];

// split (a,b) into bf16 hi-pair + lo-pair words: h = {lo=bf16(a), hi=bf16(b)}
__device__ __forceinline__ void split2(float a, float b, uint32_t& h, uint32_t& l) {
    asm("cvt.rn.bf16x2.f32 %0, %1, %2;" : "=r"(h) : "f"(b), "f"(a));
    float ha = __uint_as_float(h << 16);
    float hb = __uint_as_float(h & 0xffff0000u);
    float ra = a - ha, rb = b - hb;
    asm("cvt.rn.bf16x2.f32 %0, %1, %2;" : "=r"(l) : "f"(rb), "f"(ra));
}

static __device__ __forceinline__ uint32_t smem_u32(const void* p) {
    uint32_t a;
    asm("{ .reg .u64 t; cvta.to.shared.u64 t, %1; cvt.u32.u64 %0, t; }" : "=r"(a) : "l"(p));
    return a;
}
__device__ __forceinline__ void ldsm4(uint32_t* r, uint32_t addr) {
    asm volatile("ldmatrix.sync.aligned.m8n8.x4.shared.b16 {%0,%1,%2,%3}, [%4];"
                 : "=r"(r[0]), "=r"(r[1]), "=r"(r[2]), "=r"(r[3]) : "r"(addr));
}
__device__ __forceinline__ void ldsm4t(uint32_t* r, uint32_t addr) {
    asm volatile("ldmatrix.sync.aligned.m8n8.x4.trans.shared.b16 {%0,%1,%2,%3}, [%4];"
                 : "=r"(r[0]), "=r"(r[1]), "=r"(r[2]), "=r"(r[3]) : "r"(addr));
}
__device__ __forceinline__ void mmabf16(float* c, const uint32_t* a, uint32_t b0, uint32_t b1) {
    asm volatile("mma.sync.aligned.m16n8k16.row.col.f32.bf16.bf16.f32 "
                 "{%0,%1,%2,%3}, {%4,%5,%6,%7}, {%8,%9}, {%0,%1,%2,%3};"
                 : "+f"(c[0]), "+f"(c[1]), "+f"(c[2]), "+f"(c[3])
                 : "r"(a[0]), "r"(a[1]), "r"(a[2]), "r"(a[3]), "r"(b0), "r"(b1));
}
__device__ __forceinline__ void cpa16(uint32_t d, const void* s) {
    asm volatile("cp.async.cg.shared.global [%0], [%1], 16;" :: "r"(d), "l"(s));
}
#define CP_COMMIT() asm volatile("cp.async.commit_group;" ::: "memory")
#define CP_WAIT1()  asm volatile("cp.async.wait_group 1;" ::: "memory")

#define SW128(o) ((o) ^ (((o) >> 3) & 0x70))
#define SW64(o)  ((o) ^ (((o) >> 3) & 0x30))

// ---------------------------------------------------------------------------
// Tensor-core GEMM: C[M,512] = X[M,512] @ W^T + bias, 3-term bf16 split.
// 128x128 CTA tile, BK=32. Warp w owns rows 16w..16w+15, all 128 cols.
// mode 0: fp32 out. mode 1: bf16 hi/lo out, value = scale*(acc+bias).
// ---------------------------------------------------------------------------
__global__ __launch_bounds__(256, 2) void gemm_bf16(const float* __restrict__ X,
                                                    const float* __restrict__ W,
                                                    const float* __restrict__ bias,
                                                    float* __restrict__ Cf,
                                                    unsigned short* __restrict__ Ch,
                                                    unsigned short* __restrict__ Cl,
                                                    float scale, int mode)
{
    __shared__ char smp[32768];   // XH 8K | XL 8K | WH 8K | WL 8K
    const uint32_t sb = smem_u32(smp);
#define GXH 0
#define GXL 8192
#define GWH 16384
#define GWL 24576

    const int tid = threadIdx.x;
    const int w = tid >> 5;
    const int lane = tid & 31;
    const int m0 = blockIdx.y * 128, n0 = blockIdx.x * 128;

    const int row = tid >> 1;          // 0..127
    const int half = tid & 1;          // 64B half of the 128B fp32 row chunk

    const float* Xg = X + (size_t)(m0 + row) * DMODEL + half * 16;
    const float* Wg = W + (size_t)(n0 + row) * DMODEL + half * 16;

    // ldmatrix bases (row stride 64 B)
    const uint32_t base_a = (uint32_t)((16 * w + (lane & 15)) * 64 + (lane >> 4) * 16);
    const uint32_t base_b = (uint32_t)(((lane & 7) + ((lane & 16) >> 1)) * 64 + ((lane >> 3) & 1) * 16);

    float cs[16][4];
#pragma unroll
    for (int i = 0; i < 16; i++)
#pragma unroll
        for (int j = 0; j < 4; j++) cs[i][j] = 0.f;

    float4 xr[4], wr[4];
#pragma unroll
    for (int i = 0; i < 4; i++) {
        xr[i] = *(const float4*)(Xg + i * 4);
        wr[i] = *(const float4*)(Wg + i * 4);
    }

    for (int ks = 0; ks < DMODEL / 32; ks++) {
        __syncthreads();   // previous compute done with smem
        // split + STS (8B chunks; swizzle preserves 8B alignment)
#pragma unroll
        for (int i = 0; i < 4; i++) {
            uint32_t h0, l0, h1, l1;
            split2(xr[i].x, xr[i].y, h0, l0);
            split2(xr[i].z, xr[i].w, h1, l1);
            const uint32_t off = SW64((uint32_t)(row * 64 + half * 32 + i * 8));
            *(uint2*)(smp + GXH + off) = make_uint2(h0, h1);
            *(uint2*)(smp + GXL + off) = make_uint2(l0, l1);
            split2(wr[i].x, wr[i].y, h0, l0);
            split2(wr[i].z, wr[i].w, h1, l1);
            *(uint2*)(smp + GWH + off) = make_uint2(h0, h1);
            *(uint2*)(smp + GWL + off) = make_uint2(l0, l1);
        }
        __syncthreads();

        if (ks + 1 < DMODEL / 32) {
            const int k1 = (ks + 1) * 32;
#pragma unroll
            for (int i = 0; i < 4; i++) {
                xr[i] = *(const float4*)(Xg + k1 + i * 4);
                wr[i] = *(const float4*)(Wg + k1 + i * 4);
            }
        }

#pragma unroll
        for (int c = 0; c < 2; c++) {
            uint32_t ah[4], al[4];
            const uint32_t aoff = SW64(base_a + 32u * c);
            ldsm4(ah, sb + GXH + aoff);
            ldsm4(al, sb + GXL + aoff);
#pragma unroll
            for (int j2 = 0; j2 < 8; j2++) {
                uint32_t bh[4], bl[4];
                const uint32_t boff = SW64(base_b + 1024u * j2 + 32u * c);
                ldsm4(bh, sb + GWH + boff);
                ldsm4(bl, sb + GWL + boff);
                mmabf16(cs[2 * j2], ah, bh[0], bh[1]);
                mmabf16(cs[2 * j2], ah, bl[0], bl[1]);
                mmabf16(cs[2 * j2], al, bh[0], bh[1]);
                mmabf16(cs[2 * j2 + 1], ah, bh[2], bh[3]);
                mmabf16(cs[2 * j2 + 1], ah, bl[2], bl[3]);
                mmabf16(cs[2 * j2 + 1], al, bh[2], bh[3]);
            }
        }
    }

    // epilogue
    const int rr = m0 + 16 * w + (lane >> 2);
    const int cc = 2 * (lane & 3);
    if (mode == 0) {
#pragma unroll
        for (int t = 0; t < 16; t++) {
            const int col = n0 + 8 * t + cc;
            const float2 bv = *(const float2*)(bias + col);
            float* C0 = Cf + (size_t)rr * DMODEL + col;
            *(float2*)C0 = make_float2(cs[t][0] + bv.x, cs[t][1] + bv.y);
            *(float2*)(C0 + 8 * DMODEL) = make_float2(cs[t][2] + bv.x, cs[t][3] + bv.y);
        }
    } else {
#pragma unroll
        for (int t = 0; t < 16; t++) {
            const int col = n0 + 8 * t + cc;
            const float2 bv = *(const float2*)(bias + col);
            uint32_t h, l;
            split2(scale * (cs[t][0] + bv.x), scale * (cs[t][1] + bv.y), h, l);
            *(uint32_t*)(Ch + (size_t)rr * DMODEL + col) = h;
            *(uint32_t*)(Cl + (size_t)rr * DMODEL + col) = l;
            split2(scale * (cs[t][2] + bv.x), scale * (cs[t][3] + bv.y), h, l);
            *(uint32_t*)(Ch + (size_t)(rr + 8) * DMODEL + col) = h;
            *(uint32_t*)(Cl + (size_t)(rr + 8) * DMODEL + col) = l;
        }
    }
}

// ===========================================================================
// mma.sync attention (unchanged from round 5)
// ===========================================================================

#define OQH 0
#define OQL 16384
#define OST 32768
#define STAGE_SZ 65536
#define SKH 0
#define SKL 16384
#define SVH 32768
#define SVL 49152
#define ATTN_SMEM (OST + 2 * STAGE_SZ)

__global__ __launch_bounds__(256) void attn_kernel(
    const unsigned short* __restrict__ Qh, const unsigned short* __restrict__ Ql,
    const unsigned short* __restrict__ Kh, const unsigned short* __restrict__ Kl,
    const unsigned short* __restrict__ Vh, const unsigned short* __restrict__ Vl,
    const float* __restrict__ relpos, float* __restrict__ Out)
{
    extern __shared__ char smp[];
    const uint32_t sb = smem_u32(smp);

    const int tid = threadIdx.x;
    const int w = tid >> 5;
    const int lane = tid & 31;
    const int b = blockIdx.z, h = blockIdx.y;
    const int q0 = blockIdx.x * 128;

    const float rb0 = relpos[h * 5 + 0];
    const float rb1 = relpos[h * 5 + 1];
    const float rb2 = relpos[h * 5 + 2];
    const float rb3 = relpos[h * 5 + 3];
    const float rb4 = relpos[h * 5 + 4];

    {
        const int row = tid >> 1;
        const int ch0 = (tid & 1) * 4;
        const size_t gb = (size_t)(b * SEQ + q0 + row) * DMODEL + h * HDIM + ch0 * 8;
#pragma unroll
        for (int ci = 0; ci < 4; ci++) {
            const uint32_t off = SW128((uint32_t)(row * 128 + (ch0 + ci) * 16));
            *(uint4*)(smp + OQH + off) = *(const uint4*)(Qh + gb + ci * 8);
            *(uint4*)(smp + OQL + off) = *(const uint4*)(Ql + gb + ci * 8);
        }
    }

    const int krow = tid >> 1;
    const int kch0 = (tid & 1) * 4;
    const size_t kgb0 = (size_t)(b * SEQ + krow) * DMODEL + h * HDIM + kch0 * 8;

    {
        const uint32_t st = sb + OST;
        const size_t gb = kgb0;
#pragma unroll
        for (int ci = 0; ci < 4; ci++) {
            const uint32_t off = SW128((uint32_t)(krow * 128 + (kch0 + ci) * 16));
            cpa16(st + SKH + off, Kh + gb + ci * 8);
            cpa16(st + SKL + off, Kl + gb + ci * 8);
            cpa16(st + SVH + off, Vh + gb + ci * 8);
            cpa16(st + SVL + off, Vl + gb + ci * 8);
        }
    }
    CP_COMMIT();

    const uint32_t base_qa = (uint32_t)((16 * w + (lane & 15)) * 128 + 16 * (lane >> 4));
    const uint32_t base_kb = (uint32_t)(((lane & 7) + ((lane & 16) >> 1)) * 128 + ((lane >> 3) & 1) * 16);
    const uint32_t base_vb = (uint32_t)(((lane & 7) + (lane & 8)) * 128 + ((lane >> 4) & 1) * 16);

    float co[8][4];
#pragma unroll
    for (int i = 0; i < 8; i++)
#pragma unroll
        for (int j = 0; j < 4; j++) co[i][j] = 0.f;
    float sum0 = 0.f, sum1 = 0.f;

    const int r0g = q0 + 16 * w + (lane >> 2);
    const int kcol_off = 2 * (lane & 3);

    for (int kt = 0; kt < SEQ / 128; kt++) {
        const int k0 = kt * 128;

        if (kt + 1 < SEQ / 128) {
            const uint32_t st = sb + OST + ((kt + 1) & 1) * STAGE_SZ;
            const size_t gb = kgb0 + (size_t)(k0 + 128) * DMODEL;
#pragma unroll
            for (int ci = 0; ci < 4; ci++) {
                const uint32_t off = SW128((uint32_t)(krow * 128 + (kch0 + ci) * 16));
                cpa16(st + SKH + off, Kh + gb + ci * 8);
                cpa16(st + SKL + off, Kl + gb + ci * 8);
                cpa16(st + SVH + off, Vh + gb + ci * 8);
                cpa16(st + SVL + off, Vl + gb + ci * 8);
            }
        }
        CP_COMMIT();
        CP_WAIT1();
        __syncthreads();

        const uint32_t st = sb + OST + (kt & 1) * STAGE_SZ;
        const uint32_t KHb = st + SKH, KLb = st + SKL;
        const uint32_t VHb = st + SVH, VLb = st + SVL;
        const uint32_t QHb = sb + OQH, QLb = sb + OQL;

        float cs[16][4];
#pragma unroll
        for (int i = 0; i < 16; i++)
#pragma unroll
            for (int j = 0; j < 4; j++) cs[i][j] = 0.f;

#pragma unroll
        for (int c = 0; c < 4; c++) {
            uint32_t ah[4], al[4];
            ldsm4(ah, QHb + SW128(base_qa + 32 * c));
            ldsm4(al, QLb + SW128(base_qa + 32 * c));
#pragma unroll
            for (int j2 = 0; j2 < 8; j2++) {
                uint32_t bh[4], bl[4];
                const uint32_t off = SW128(base_kb + 2048u * j2 + 32u * c);
                ldsm4(bh, KHb + off);
                ldsm4(bl, KLb + off);
                mmabf16(cs[2 * j2], ah, bh[0], bh[1]);
                mmabf16(cs[2 * j2], ah, bl[0], bl[1]);
                mmabf16(cs[2 * j2], al, bh[0], bh[1]);
                mmabf16(cs[2 * j2 + 1], ah, bh[2], bh[3]);
                mmabf16(cs[2 * j2 + 1], ah, bl[2], bl[3]);
                mmabf16(cs[2 * j2 + 1], al, bh[2], bh[3]);
            }
        }

        const bool uni = (k0 - (q0 + 127) > MAXREL) || ((k0 + 127) - q0 < -MAXREL);
        if (uni) {
            const float ub = (k0 > q0) ? rb4 : rb0;
#pragma unroll
            for (int j = 0; j < 16; j++) {
                cs[j][0] = __expf(cs[j][0] + ub);
                cs[j][1] = __expf(cs[j][1] + ub);
                cs[j][2] = __expf(cs[j][2] + ub);
                cs[j][3] = __expf(cs[j][3] + ub);
            }
        } else {
#pragma unroll
            for (int j = 0; j < 16; j++) {
                const int kc = k0 + 8 * j + kcol_off;
#pragma unroll
                for (int i = 0; i < 4; i++) {
                    const int rel = (kc + (i & 1)) - (r0g + (i >> 1) * 8);
                    const float bb = rel <= -MAXREL ? rb0 :
                                     rel >= MAXREL ? rb4 :
                                     rel == -1 ? rb1 : (rel == 0 ? rb2 : rb3);
                    cs[j][i] = __expf(cs[j][i] + bb);
                }
            }
        }
#pragma unroll
        for (int j = 0; j < 16; j++) {
            sum0 += cs[j][0] + cs[j][1];
            sum1 += cs[j][2] + cs[j][3];
        }

#pragma unroll
        for (int kc = 0; kc < 8; kc++) {
            uint32_t ph[4], pl[4];
            split2(cs[2 * kc][0], cs[2 * kc][1], ph[0], pl[0]);
            split2(cs[2 * kc][2], cs[2 * kc][3], ph[1], pl[1]);
            split2(cs[2 * kc + 1][0], cs[2 * kc + 1][1], ph[2], pl[2]);
            split2(cs[2 * kc + 1][2], cs[2 * kc + 1][3], ph[3], pl[3]);
#pragma unroll
            for (int jv = 0; jv < 4; jv++) {
                uint32_t vh[4], vl[4];
                const uint32_t off = SW128(base_vb + 2048u * kc + 32u * jv);
                ldsm4t(vh, VHb + off);
                ldsm4t(vl, VLb + off);
                mmabf16(co[2 * jv], ph, vh[0], vh[1]);
                mmabf16(co[2 * jv], ph, vl[0], vl[1]);
                mmabf16(co[2 * jv], pl, vh[0], vh[1]);
                mmabf16(co[2 * jv + 1], ph, vh[2], vh[3]);
                mmabf16(co[2 * jv + 1], ph, vl[2], vl[3]);
                mmabf16(co[2 * jv + 1], pl, vh[2], vh[3]);
            }
        }
        __syncthreads();
    }

    sum0 += __shfl_xor_sync(0xFFFFFFFFu, sum0, 1);
    sum0 += __shfl_xor_sync(0xFFFFFFFFu, sum0, 2);
    sum1 += __shfl_xor_sync(0xFFFFFFFFu, sum1, 1);
    sum1 += __shfl_xor_sync(0xFFFFFFFFu, sum1, 2);
    const float inv0 = 1.0f / sum0;
    const float inv1 = 1.0f / sum1;

    {
        float* O0 = Out + (size_t)(b * SEQ + r0g) * DMODEL + h * HDIM + kcol_off;
        float* O1 = O0 + 8 * DMODEL;
#pragma unroll
        for (int j = 0; j < 8; j++) {
            *(float2*)(O0 + 8 * j) = make_float2(co[j][0] * inv0, co[j][1] * inv0);
            *(float2*)(O1 + 8 * j) = make_float2(co[j][2] * inv1, co[j][3] * inv1);
        }
    }
}

// ---------------------------------------------------------------------------
extern "C" void kernel_launch(void* const* d_in, const int* in_sizes, int n_in,
                              void* d_out, int out_size)
{
    const float* q  = (const float*)d_in[0];
    const float* k  = (const float*)d_in[1];
    const float* v  = (const float*)d_in[2];
    const float* Wq = (const float*)d_in[3];
    const float* bq = (const float*)d_in[4];
    const float* Wk = (const float*)d_in[5];
    const float* bk = (const float*)d_in[6];
    const float* Wv = (const float*)d_in[7];
    const float* bv = (const float*)d_in[8];
    const float* Wo = (const float*)d_in[9];
    const float* bo = (const float*)d_in[10];
    const float* rp = (const float*)d_in[11];
    float* out = (float*)d_out;

    float *dA;
    unsigned short *dQh, *dQl, *dKh, *dKl, *dVh, *dVl;
    cudaGetSymbolAddress((void**)&dA, g_A);
    cudaGetSymbolAddress((void**)&dQh, g_Qh);
    cudaGetSymbolAddress((void**)&dQl, g_Ql);
    cudaGetSymbolAddress((void**)&dKh, g_Kh);
    cudaGetSymbolAddress((void**)&dKl, g_Kl);
    cudaGetSymbolAddress((void**)&dVh, g_Vh);
    cudaGetSymbolAddress((void**)&dVl, g_Vl);

    cudaFuncSetAttribute(attn_kernel, cudaFuncAttributeMaxDynamicSharedMemorySize,
                         ATTN_SMEM);

    dim3 gblk(256);
    dim3 ggrid(DMODEL / 128, MROWS / 128);   // (4, 64)

    gemm_bf16<<<ggrid, gblk>>>(q, Wq, bq, nullptr, dQh, dQl, 0.125f, 1);
    gemm_bf16<<<ggrid, gblk>>>(k, Wk, bk, nullptr, dKh, dKl, 1.0f, 1);
    gemm_bf16<<<ggrid, gblk>>>(v, Wv, bv, nullptr, dVh, dVl, 1.0f, 1);

    dim3 agrid(SEQ / 128, NHEAD, BATCH);     // (32, 8, 2)
    attn_kernel<<<agrid, gblk, ATTN_SMEM>>>(dQh, dQl, dKh, dKl, dVh, dVl, rp, dA);

    gemm_bf16<<<ggrid, gblk>>>(dA, Wo, bo, out, nullptr, nullptr, 1.0f, 0);
}

// round 7
// speedup vs baseline: 3.2093x; 1.1064x over previous
#include <cuda_runtime.h>
#include <cuda_bf16.h>
#include <math.h>
#include <stdint.h>

#define BATCH 2
#define SEQ   4096
#define DMODEL 512
#define NHEAD 8
#define HDIM  64
#define MROWS (BATCH*SEQ)
#define MAXREL 2

typedef unsigned long long ull;

// scratch
__device__ float g_A[MROWS * DMODEL];
__device__ unsigned short g_Qh[MROWS * DMODEL];
__device__ unsigned short g_Ql[MROWS * DMODEL];
__device__ unsigned short g_Kh[MROWS * DMODEL];
__device__ unsigned short g_Kl[MROWS * DMODEL];
__device__ unsigned short g_Vh[MROWS * DMODEL];
__device__ unsigned short g_Vl[MROWS * DMODEL];

// split (a,b) into bf16 hi-pair + lo-pair words: h = {lo=bf16(a), hi=bf16(b)}
__device__ __forceinline__ void split2(float a, float b, uint32_t& h, uint32_t& l) {
    asm("cvt.rn.bf16x2.f32 %0, %1, %2;" : "=r"(h) : "f"(b), "f"(a));
    float ha = __uint_as_float(h << 16);
    float hb = __uint_as_float(h & 0xffff0000u);
    float ra = a - ha, rb = b - hb;
    asm("cvt.rn.bf16x2.f32 %0, %1, %2;" : "=r"(l) : "f"(rb), "f"(ra));
}

static __device__ __forceinline__ uint32_t smem_u32(const void* p) {
    uint32_t a;
    asm("{ .reg .u64 t; cvta.to.shared.u64 t, %1; cvt.u32.u64 %0, t; }" : "=r"(a) : "l"(p));
    return a;
}
__device__ __forceinline__ void ldsm4(uint32_t* r, uint32_t addr) {
    asm volatile("ldmatrix.sync.aligned.m8n8.x4.shared.b16 {%0,%1,%2,%3}, [%4];"
                 : "=r"(r[0]), "=r"(r[1]), "=r"(r[2]), "=r"(r[3]) : "r"(addr));
}
__device__ __forceinline__ void ldsm4t(uint32_t* r, uint32_t addr) {
    asm volatile("ldmatrix.sync.aligned.m8n8.x4.trans.shared.b16 {%0,%1,%2,%3}, [%4];"
                 : "=r"(r[0]), "=r"(r[1]), "=r"(r[2]), "=r"(r[3]) : "r"(addr));
}
__device__ __forceinline__ void mmabf16(float* c, const uint32_t* a, uint32_t b0, uint32_t b1) {
    asm volatile("mma.sync.aligned.m16n8k16.row.col.f32.bf16.bf16.f32 "
                 "{%0,%1,%2,%3}, {%4,%5,%6,%7}, {%8,%9}, {%0,%1,%2,%3};"
                 : "+f"(c[0]), "+f"(c[1]), "+f"(c[2]), "+f"(c[3])
                 : "r"(a[0]), "r"(a[1]), "r"(a[2]), "r"(a[3]), "r"(b0), "r"(b1));
}
__device__ __forceinline__ void cpa16(uint32_t d, const void* s) {
    asm volatile("cp.async.cg.shared.global [%0], [%1], 16;" :: "r"(d), "l"(s));
}
#define CP_COMMIT() asm volatile("cp.async.commit_group;" ::: "memory")
#define CP_WAIT1()  asm volatile("cp.async.wait_group 1;" ::: "memory")

#define SW128(o) ((o) ^ (((o) >> 3) & 0x70))
#define SW64(o)  ((o) ^ (((o) >> 3) & 0x30))

// ---------------------------------------------------------------------------
// Tensor-core GEMM (unchanged from round 6)
// ---------------------------------------------------------------------------
__global__ __launch_bounds__(256, 2) void gemm_bf16(const float* __restrict__ X,
                                                    const float* __restrict__ W,
                                                    const float* __restrict__ bias,
                                                    float* __restrict__ Cf,
                                                    unsigned short* __restrict__ Ch,
                                                    unsigned short* __restrict__ Cl,
                                                    float scale, int mode)
{
    __shared__ char smp[32768];
    const uint32_t sb = smem_u32(smp);
#define GXH 0
#define GXL 8192
#define GWH 16384
#define GWL 24576

    const int tid = threadIdx.x;
    const int w = tid >> 5;
    const int lane = tid & 31;
    const int m0 = blockIdx.y * 128, n0 = blockIdx.x * 128;

    const int row = tid >> 1;
    const int half = tid & 1;

    const float* Xg = X + (size_t)(m0 + row) * DMODEL + half * 16;
    const float* Wg = W + (size_t)(n0 + row) * DMODEL + half * 16;

    const uint32_t base_a = (uint32_t)((16 * w + (lane & 15)) * 64 + (lane >> 4) * 16);
    const uint32_t base_b = (uint32_t)(((lane & 7) + ((lane & 16) >> 1)) * 64 + ((lane >> 3) & 1) * 16);

    float cs[16][4];
#pragma unroll
    for (int i = 0; i < 16; i++)
#pragma unroll
        for (int j = 0; j < 4; j++) cs[i][j] = 0.f;

    float4 xr[4], wr[4];
#pragma unroll
    for (int i = 0; i < 4; i++) {
        xr[i] = *(const float4*)(Xg + i * 4);
        wr[i] = *(const float4*)(Wg + i * 4);
    }

    for (int ks = 0; ks < DMODEL / 32; ks++) {
        __syncthreads();
#pragma unroll
        for (int i = 0; i < 4; i++) {
            uint32_t h0, l0, h1, l1;
            split2(xr[i].x, xr[i].y, h0, l0);
            split2(xr[i].z, xr[i].w, h1, l1);
            const uint32_t off = SW64((uint32_t)(row * 64 + half * 32 + i * 8));
            *(uint2*)(smp + GXH + off) = make_uint2(h0, h1);
            *(uint2*)(smp + GXL + off) = make_uint2(l0, l1);
            split2(wr[i].x, wr[i].y, h0, l0);
            split2(wr[i].z, wr[i].w, h1, l1);
            *(uint2*)(smp + GWH + off) = make_uint2(h0, h1);
            *(uint2*)(smp + GWL + off) = make_uint2(l0, l1);
        }
        __syncthreads();

        if (ks + 1 < DMODEL / 32) {
            const int k1 = (ks + 1) * 32;
#pragma unroll
            for (int i = 0; i < 4; i++) {
                xr[i] = *(const float4*)(Xg + k1 + i * 4);
                wr[i] = *(const float4*)(Wg + k1 + i * 4);
            }
        }

#pragma unroll
        for (int c = 0; c < 2; c++) {
            uint32_t ah[4], al[4];
            const uint32_t aoff = SW64(base_a + 32u * c);
            ldsm4(ah, sb + GXH + aoff);
            ldsm4(al, sb + GXL + aoff);
#pragma unroll
            for (int j2 = 0; j2 < 8; j2++) {
                uint32_t bh[4], bl[4];
                const uint32_t boff = SW64(base_b + 1024u * j2 + 32u * c);
                ldsm4(bh, sb + GWH + boff);
                ldsm4(bl, sb + GWL + boff);
                mmabf16(cs[2 * j2], ah, bh[0], bh[1]);
                mmabf16(cs[2 * j2], ah, bl[0], bl[1]);
                mmabf16(cs[2 * j2], al, bh[0], bh[1]);
                mmabf16(cs[2 * j2 + 1], ah, bh[2], bh[3]);
                mmabf16(cs[2 * j2 + 1], ah, bl[2], bl[3]);
                mmabf16(cs[2 * j2 + 1], al, bh[2], bh[3]);
            }
        }
    }

    const int rr = m0 + 16 * w + (lane >> 2);
    const int cc = 2 * (lane & 3);
    if (mode == 0) {
#pragma unroll
        for (int t = 0; t < 16; t++) {
            const int col = n0 + 8 * t + cc;
            const float2 bv = *(const float2*)(bias + col);
            float* C0 = Cf + (size_t)rr * DMODEL + col;
            *(float2*)C0 = make_float2(cs[t][0] + bv.x, cs[t][1] + bv.y);
            *(float2*)(C0 + 8 * DMODEL) = make_float2(cs[t][2] + bv.x, cs[t][3] + bv.y);
        }
    } else {
#pragma unroll
        for (int t = 0; t < 16; t++) {
            const int col = n0 + 8 * t + cc;
            const float2 bv = *(const float2*)(bias + col);
            uint32_t h, l;
            split2(scale * (cs[t][0] + bv.x), scale * (cs[t][1] + bv.y), h, l);
            *(uint32_t*)(Ch + (size_t)rr * DMODEL + col) = h;
            *(uint32_t*)(Cl + (size_t)rr * DMODEL + col) = l;
            split2(scale * (cs[t][2] + bv.x), scale * (cs[t][3] + bv.y), h, l);
            *(uint32_t*)(Ch + (size_t)(rr + 8) * DMODEL + col) = h;
            *(uint32_t*)(Cl + (size_t)(rr + 8) * DMODEL + col) = l;
        }
    }
}

// ===========================================================================
// mma.sync attention — KV tile 64, double-buffered, 96KB smem, 2 CTAs/SM
// ===========================================================================

#define OQH 0
#define OQL 16384
#define OST 32768
#define STAGE_SZ 32768
#define SKH 0
#define SKL 8192
#define SVH 16384
#define SVL 24576
#define ATTN_SMEM (OST + 2 * STAGE_SZ)
#define NKT (SEQ / 64)

__global__ __launch_bounds__(256, 2) void attn_kernel(
    const unsigned short* __restrict__ Qh, const unsigned short* __restrict__ Ql,
    const unsigned short* __restrict__ Kh, const unsigned short* __restrict__ Kl,
    const unsigned short* __restrict__ Vh, const unsigned short* __restrict__ Vl,
    const float* __restrict__ relpos, float* __restrict__ Out)
{
    extern __shared__ char smp[];
    const uint32_t sb = smem_u32(smp);

    const int tid = threadIdx.x;
    const int w = tid >> 5;
    const int lane = tid & 31;
    const int b = blockIdx.z, h = blockIdx.y;
    const int q0 = blockIdx.x * 128;

    const float rb0 = relpos[h * 5 + 0];
    const float rb1 = relpos[h * 5 + 1];
    const float rb2 = relpos[h * 5 + 2];
    const float rb3 = relpos[h * 5 + 3];
    const float rb4 = relpos[h * 5 + 4];

    // Q tile load (128 rows x 128B, SW128)
    {
        const int row = tid >> 1;
        const int ch0 = (tid & 1) * 4;
        const size_t gb = (size_t)(b * SEQ + q0 + row) * DMODEL + h * HDIM + ch0 * 8;
#pragma unroll
        for (int ci = 0; ci < 4; ci++) {
            const uint32_t off = SW128((uint32_t)(row * 128 + (ch0 + ci) * 16));
            *(uint4*)(smp + OQH + off) = *(const uint4*)(Qh + gb + ci * 8);
            *(uint4*)(smp + OQL + off) = *(const uint4*)(Ql + gb + ci * 8);
        }
    }

    // K/V tile loader: 64 rows x 128B per array; thread -> row=tid>>2, 2x16B chunks
    const int krow = tid >> 2;
    const int kch = tid & 3;                  // 2 chunks: kch*32, kch*32+16 bytes
    const size_t kgb0 = (size_t)(b * SEQ + krow) * DMODEL + h * HDIM + kch * 16;

    {
        const uint32_t st = sb + OST;
        const uint32_t off0 = SW128((uint32_t)(krow * 128 + kch * 32));
        const uint32_t off1 = SW128((uint32_t)(krow * 128 + kch * 32 + 16));
        cpa16(st + SKH + off0, Kh + kgb0);     cpa16(st + SKH + off1, Kh + kgb0 + 8);
        cpa16(st + SKL + off0, Kl + kgb0);     cpa16(st + SKL + off1, Kl + kgb0 + 8);
        cpa16(st + SVH + off0, Vh + kgb0);     cpa16(st + SVH + off1, Vh + kgb0 + 8);
        cpa16(st + SVL + off0, Vl + kgb0);     cpa16(st + SVL + off1, Vl + kgb0 + 8);
    }
    CP_COMMIT();

    const uint32_t base_qa = (uint32_t)((16 * w + (lane & 15)) * 128 + 16 * (lane >> 4));
    const uint32_t base_kb = (uint32_t)(((lane & 7) + ((lane & 16) >> 1)) * 128 + ((lane >> 3) & 1) * 16);
    const uint32_t base_vb = (uint32_t)(((lane & 7) + (lane & 8)) * 128 + ((lane >> 4) & 1) * 16);

    float co[8][4];
#pragma unroll
    for (int i = 0; i < 8; i++)
#pragma unroll
        for (int j = 0; j < 4; j++) co[i][j] = 0.f;
    float sum0 = 0.f, sum1 = 0.f;

    const int r0g = q0 + 16 * w + (lane >> 2);
    const int kcol_off = 2 * (lane & 3);

    for (int kt = 0; kt < NKT; kt++) {
        const int k0 = kt * 64;

        if (kt + 1 < NKT) {
            const uint32_t st = sb + OST + ((kt + 1) & 1) * STAGE_SZ;
            const size_t gb = kgb0 + (size_t)(k0 + 64) * DMODEL;
            const uint32_t off0 = SW128((uint32_t)(krow * 128 + kch * 32));
            const uint32_t off1 = SW128((uint32_t)(krow * 128 + kch * 32 + 16));
            cpa16(st + SKH + off0, Kh + gb);     cpa16(st + SKH + off1, Kh + gb + 8);
            cpa16(st + SKL + off0, Kl + gb);     cpa16(st + SKL + off1, Kl + gb + 8);
            cpa16(st + SVH + off0, Vh + gb);     cpa16(st + SVH + off1, Vh + gb + 8);
            cpa16(st + SVL + off0, Vl + gb);     cpa16(st + SVL + off1, Vl + gb + 8);
        }
        CP_COMMIT();
        CP_WAIT1();
        __syncthreads();

        const uint32_t st = sb + OST + (kt & 1) * STAGE_SZ;
        const uint32_t KHb = st + SKH, KLb = st + SKL;
        const uint32_t VHb = st + SVH, VLb = st + SVL;
        const uint32_t QHb = sb + OQH, QLb = sb + OQL;

        // ---- S = Q @ K^T (3-term bf16): 4 hd-chunks x 4 key-16 blocks ----
        float cs[8][4];
#pragma unroll
        for (int i = 0; i < 8; i++)
#pragma unroll
            for (int j = 0; j < 4; j++) cs[i][j] = 0.f;

#pragma unroll
        for (int c = 0; c < 4; c++) {
            uint32_t ah[4], al[4];
            ldsm4(ah, QHb + SW128(base_qa + 32 * c));
            ldsm4(al, QLb + SW128(base_qa + 32 * c));
#pragma unroll
            for (int j2 = 0; j2 < 4; j2++) {
                uint32_t bh[4], bl[4];
                const uint32_t off = SW128(base_kb + 2048u * j2 + 32u * c);
                ldsm4(bh, KHb + off);
                ldsm4(bl, KLb + off);
                mmabf16(cs[2 * j2], ah, bh[0], bh[1]);
                mmabf16(cs[2 * j2], ah, bl[0], bl[1]);
                mmabf16(cs[2 * j2], al, bh[0], bh[1]);
                mmabf16(cs[2 * j2 + 1], ah, bh[2], bh[3]);
                mmabf16(cs[2 * j2 + 1], ah, bl[2], bl[3]);
                mmabf16(cs[2 * j2 + 1], al, bh[2], bh[3]);
            }
        }

        // ---- bias + exp + rowsum ----
        const bool uni = (k0 - (q0 + 127) > MAXREL) || ((k0 + 63) - q0 < -MAXREL);
        if (uni) {
            const float ub = (k0 > q0) ? rb4 : rb0;
#pragma unroll
            for (int j = 0; j < 8; j++) {
                cs[j][0] = __expf(cs[j][0] + ub);
                cs[j][1] = __expf(cs[j][1] + ub);
                cs[j][2] = __expf(cs[j][2] + ub);
                cs[j][3] = __expf(cs[j][3] + ub);
            }
        } else {
#pragma unroll
            for (int j = 0; j < 8; j++) {
                const int kc = k0 + 8 * j + kcol_off;
#pragma unroll
                for (int i = 0; i < 4; i++) {
                    const int rel = (kc + (i & 1)) - (r0g + (i >> 1) * 8);
                    const float bb = rel <= -MAXREL ? rb0 :
                                     rel >= MAXREL ? rb4 :
                                     rel == -1 ? rb1 : (rel == 0 ? rb2 : rb3);
                    cs[j][i] = __expf(cs[j][i] + bb);
                }
            }
        }
#pragma unroll
        for (int j = 0; j < 8; j++) {
            sum0 += cs[j][0] + cs[j][1];
            sum1 += cs[j][2] + cs[j][3];
        }

        // ---- O += P @ V (3-term bf16, P from registers) ----
#pragma unroll
        for (int kc = 0; kc < 4; kc++) {
            uint32_t ph[4], pl[4];
            split2(cs[2 * kc][0], cs[2 * kc][1], ph[0], pl[0]);
            split2(cs[2 * kc][2], cs[2 * kc][3], ph[1], pl[1]);
            split2(cs[2 * kc + 1][0], cs[2 * kc + 1][1], ph[2], pl[2]);
            split2(cs[2 * kc + 1][2], cs[2 * kc + 1][3], ph[3], pl[3]);
#pragma unroll
            for (int jv = 0; jv < 4; jv++) {
                uint32_t vh[4], vl[4];
                const uint32_t off = SW128(base_vb + 2048u * kc + 32u * jv);
                ldsm4t(vh, VHb + off);
                ldsm4t(vl, VLb + off);
                mmabf16(co[2 * jv], ph, vh[0], vh[1]);
                mmabf16(co[2 * jv], ph, vl[0], vl[1]);
                mmabf16(co[2 * jv], pl, vh[0], vh[1]);
                mmabf16(co[2 * jv + 1], ph, vh[2], vh[3]);
                mmabf16(co[2 * jv + 1], ph, vl[2], vl[3]);
                mmabf16(co[2 * jv + 1], pl, vh[2], vh[3]);
            }
        }
        __syncthreads();
    }

    sum0 += __shfl_xor_sync(0xFFFFFFFFu, sum0, 1);
    sum0 += __shfl_xor_sync(0xFFFFFFFFu, sum0, 2);
    sum1 += __shfl_xor_sync(0xFFFFFFFFu, sum1, 1);
    sum1 += __shfl_xor_sync(0xFFFFFFFFu, sum1, 2);
    const float inv0 = 1.0f / sum0;
    const float inv1 = 1.0f / sum1;

    {
        float* O0 = Out + (size_t)(b * SEQ + r0g) * DMODEL + h * HDIM + kcol_off;
        float* O1 = O0 + 8 * DMODEL;
#pragma unroll
        for (int j = 0; j < 8; j++) {
            *(float2*)(O0 + 8 * j) = make_float2(co[j][0] * inv0, co[j][1] * inv0);
            *(float2*)(O1 + 8 * j) = make_float2(co[j][2] * inv1, co[j][3] * inv1);
        }
    }
}

// ---------------------------------------------------------------------------
extern "C" void kernel_launch(void* const* d_in, const int* in_sizes, int n_in,
                              void* d_out, int out_size)
{
    const float* q  = (const float*)d_in[0];
    const float* k  = (const float*)d_in[1];
    const float* v  = (const float*)d_in[2];
    const float* Wq = (const float*)d_in[3];
    const float* bq = (const float*)d_in[4];
    const float* Wk = (const float*)d_in[5];
    const float* bk = (const float*)d_in[6];
    const float* Wv = (const float*)d_in[7];
    const float* bv = (const float*)d_in[8];
    const float* Wo = (const float*)d_in[9];
    const float* bo = (const float*)d_in[10];
    const float* rp = (const float*)d_in[11];
    float* out = (float*)d_out;

    float *dA;
    unsigned short *dQh, *dQl, *dKh, *dKl, *dVh, *dVl;
    cudaGetSymbolAddress((void**)&dA, g_A);
    cudaGetSymbolAddress((void**)&dQh, g_Qh);
    cudaGetSymbolAddress((void**)&dQl, g_Ql);
    cudaGetSymbolAddress((void**)&dKh, g_Kh);
    cudaGetSymbolAddress((void**)&dKl, g_Kl);
    cudaGetSymbolAddress((void**)&dVh, g_Vh);
    cudaGetSymbolAddress((void**)&dVl, g_Vl);

    cudaFuncSetAttribute(attn_kernel, cudaFuncAttributeMaxDynamicSharedMemorySize,
                         ATTN_SMEM);

    dim3 gblk(256);
    dim3 ggrid(DMODEL / 128, MROWS / 128);   // (4, 64)

    gemm_bf16<<<ggrid, gblk>>>(q, Wq, bq, nullptr, dQh, dQl, 0.125f, 1);
    gemm_bf16<<<ggrid, gblk>>>(k, Wk, bk, nullptr, dKh, dKl, 1.0f, 1);
    gemm_bf16<<<ggrid, gblk>>>(v, Wv, bv, nullptr, dVh, dVl, 1.0f, 1);

    dim3 agrid(SEQ / 128, NHEAD, BATCH);     // (32, 8, 2)
    attn_kernel<<<agrid, gblk, ATTN_SMEM>>>(dQh, dQl, dKh, dKl, dVh, dVl, rp, dA);

    gemm_bf16<<<ggrid, gblk>>>(dA, Wo, bo, out, nullptr, nullptr, 1.0f, 0);
}

// round 11
// speedup vs baseline: 5.5678x; 1.7349x over previous
#include <cuda_runtime.h>
#include <cuda_bf16.h>
#include <cuda_fp16.h>
#include <math.h>
#include <stdint.h>

#define BATCH 2
#define SEQ   4096
#define DMODEL 512
#define NHEAD 8
#define HDIM  64
#define MROWS (BATCH*SEQ)
#define MAXREL 2

typedef unsigned long long ull;

// scratch
__device__ float g_A[MROWS * DMODEL];
__device__ unsigned short g_Qh[MROWS * DMODEL];   // fp16
__device__ unsigned short g_Kh[MROWS * DMODEL];   // fp16
__device__ unsigned short g_Vh[MROWS * DMODEL];   // fp16

// split (a,b) into bf16 hi-pair + lo-pair words (GEMM internals): h={lo=a,hi=b}
__device__ __forceinline__ void split2(float a, float b, uint32_t& h, uint32_t& l) {
    asm("cvt.rn.bf16x2.f32 %0, %1, %2;" : "=r"(h) : "f"(b), "f"(a));
    float ha = __uint_as_float(h << 16);
    float hb = __uint_as_float(h & 0xffff0000u);
    float ra = a - ha, rb = b - hb;
    asm("cvt.rn.bf16x2.f32 %0, %1, %2;" : "=r"(l) : "f"(rb), "f"(ra));
}
// pack (a,b) -> fp16x2 {lo=a, hi=b}
__device__ __forceinline__ uint32_t pkhf2(float a, float b) {
    uint32_t h;
    asm("cvt.rn.f16x2.f32 %0, %1, %2;" : "=r"(h) : "f"(b), "f"(a));
    return h;
}

static __device__ __forceinline__ uint32_t smem_u32(const void* p) {
    uint32_t a;
    asm("{ .reg .u64 t; cvta.to.shared.u64 t, %1; cvt.u32.u64 %0, t; }" : "=r"(a) : "l"(p));
    return a;
}
__device__ __forceinline__ void ldsm4(uint32_t* r, uint32_t addr) {
    asm volatile("ldmatrix.sync.aligned.m8n8.x4.shared.b16 {%0,%1,%2,%3}, [%4];"
                 : "=r"(r[0]), "=r"(r[1]), "=r"(r[2]), "=r"(r[3]) : "r"(addr));
}
__device__ __forceinline__ void ldsm4t(uint32_t* r, uint32_t addr) {
    asm volatile("ldmatrix.sync.aligned.m8n8.x4.trans.shared.b16 {%0,%1,%2,%3}, [%4];"
                 : "=r"(r[0]), "=r"(r[1]), "=r"(r[2]), "=r"(r[3]) : "r"(addr));
}
// bf16 mma (GEMM)
__device__ __forceinline__ void mmabf16(float* c, const uint32_t* a, uint32_t b0, uint32_t b1) {
    asm volatile("mma.sync.aligned.m16n8k16.row.col.f32.bf16.bf16.f32 "
                 "{%0,%1,%2,%3}, {%4,%5,%6,%7}, {%8,%9}, {%0,%1,%2,%3};"
                 : "+f"(c[0]), "+f"(c[1]), "+f"(c[2]), "+f"(c[3])
                 : "r"(a[0]), "r"(a[1]), "r"(a[2]), "r"(a[3]), "r"(b0), "r"(b1));
}
// fp16 mma (attention)
__device__ __forceinline__ void mmaf16(float* c, const uint32_t* a, uint32_t b0, uint32_t b1) {
    asm volatile("mma.sync.aligned.m16n8k16.row.col.f32.f16.f16.f32 "
                 "{%0,%1,%2,%3}, {%4,%5,%6,%7}, {%8,%9}, {%0,%1,%2,%3};"
                 : "+f"(c[0]), "+f"(c[1]), "+f"(c[2]), "+f"(c[3])
                 : "r"(a[0]), "r"(a[1]), "r"(a[2]), "r"(a[3]), "r"(b0), "r"(b1));
}
__device__ __forceinline__ void cpa16(uint32_t d, const void* s) {
    asm volatile("cp.async.cg.shared.global [%0], [%1], 16;" :: "r"(d), "l"(s));
}
#define CP_COMMIT() asm volatile("cp.async.commit_group;" ::: "memory")
#define CP_WAIT2()  asm volatile("cp.async.wait_group 2;" ::: "memory")

#define SW128(o) ((o) ^ (((o) >> 3) & 0x70))
#define SW64(o)  ((o) ^ (((o) >> 3) & 0x30))

// ---------------------------------------------------------------------------
// Tensor-core GEMM, 3-term bf16 split internals (exact path).
// mode 0: fp32 out.  mode 1: fp16 out, value = scale*(acc+bias).
// ---------------------------------------------------------------------------
__global__ __launch_bounds__(256, 2) void gemm_bf16(const float* __restrict__ X,
                                                    const float* __restrict__ W,
                                                    const float* __restrict__ bias,
                                                    float* __restrict__ Cf,
                                                    unsigned short* __restrict__ Ch,
                                                    float scale, int mode)
{
    __shared__ char smp[32768];
    const uint32_t sb = smem_u32(smp);
#define GXH 0
#define GXL 8192
#define GWH 16384
#define GWL 24576

    const int tid = threadIdx.x;
    const int w = tid >> 5;
    const int lane = tid & 31;
    const int m0 = blockIdx.y * 128, n0 = blockIdx.x * 128;

    const int row = tid >> 1;
    const int half = tid & 1;

    const float* Xg = X + (size_t)(m0 + row) * DMODEL + half * 16;
    const float* Wg = W + (size_t)(n0 + row) * DMODEL + half * 16;

    const uint32_t base_a = (uint32_t)((16 * w + (lane & 15)) * 64 + (lane >> 4) * 16);
    const uint32_t base_b = (uint32_t)(((lane & 7) + ((lane & 16) >> 1)) * 64 + ((lane >> 3) & 1) * 16);

    float cs[16][4];
#pragma unroll
    for (int i = 0; i < 16; i++)
#pragma unroll
        for (int j = 0; j < 4; j++) cs[i][j] = 0.f;

    float4 xr[4], wr[4];
#pragma unroll
    for (int i = 0; i < 4; i++) {
        xr[i] = *(const float4*)(Xg + i * 4);
        wr[i] = *(const float4*)(Wg + i * 4);
    }

    for (int ks = 0; ks < DMODEL / 32; ks++) {
        __syncthreads();
#pragma unroll
        for (int i = 0; i < 4; i++) {
            uint32_t h0, l0, h1, l1;
            split2(xr[i].x, xr[i].y, h0, l0);
            split2(xr[i].z, xr[i].w, h1, l1);
            const uint32_t off = SW64((uint32_t)(row * 64 + half * 32 + i * 8));
            *(uint2*)(smp + GXH + off) = make_uint2(h0, h1);
            *(uint2*)(smp + GXL + off) = make_uint2(l0, l1);
            split2(wr[i].x, wr[i].y, h0, l0);
            split2(wr[i].z, wr[i].w, h1, l1);
            *(uint2*)(smp + GWH + off) = make_uint2(h0, h1);
            *(uint2*)(smp + GWL + off) = make_uint2(l0, l1);
        }
        __syncthreads();

        if (ks + 1 < DMODEL / 32) {
            const int k1 = (ks + 1) * 32;
#pragma unroll
            for (int i = 0; i < 4; i++) {
                xr[i] = *(const float4*)(Xg + k1 + i * 4);
                wr[i] = *(const float4*)(Wg + k1 + i * 4);
            }
        }

#pragma unroll
        for (int c = 0; c < 2; c++) {
            uint32_t ah[4], al[4];
            const uint32_t aoff = SW64(base_a + 32u * c);
            ldsm4(ah, sb + GXH + aoff);
            ldsm4(al, sb + GXL + aoff);
#pragma unroll
            for (int j2 = 0; j2 < 8; j2++) {
                uint32_t bh[4], bl[4];
                const uint32_t boff = SW64(base_b + 1024u * j2 + 32u * c);
                ldsm4(bh, sb + GWH + boff);
                ldsm4(bl, sb + GWL + boff);
                mmabf16(cs[2 * j2], ah, bh[0], bh[1]);
                mmabf16(cs[2 * j2], ah, bl[0], bl[1]);
                mmabf16(cs[2 * j2], al, bh[0], bh[1]);
                mmabf16(cs[2 * j2 + 1], ah, bh[2], bh[3]);
                mmabf16(cs[2 * j2 + 1], ah, bl[2], bl[3]);
                mmabf16(cs[2 * j2 + 1], al, bh[2], bh[3]);
            }
        }
    }

    const int rr = m0 + 16 * w + (lane >> 2);
    const int cc = 2 * (lane & 3);
    if (mode == 0) {
#pragma unroll
        for (int t = 0; t < 16; t++) {
            const int col = n0 + 8 * t + cc;
            const float2 bv = *(const float2*)(bias + col);
            float* C0 = Cf + (size_t)rr * DMODEL + col;
            *(float2*)C0 = make_float2(cs[t][0] + bv.x, cs[t][1] + bv.y);
            *(float2*)(C0 + 8 * DMODEL) = make_float2(cs[t][2] + bv.x, cs[t][3] + bv.y);
        }
    } else {
#pragma unroll
        for (int t = 0; t < 16; t++) {
            const int col = n0 + 8 * t + cc;
            const float2 bv = *(const float2*)(bias + col);
            *(uint32_t*)(Ch + (size_t)rr * DMODEL + col) =
                pkhf2(scale * (cs[t][0] + bv.x), scale * (cs[t][1] + bv.y));
            *(uint32_t*)(Ch + (size_t)(rr + 8) * DMODEL + col) =
                pkhf2(scale * (cs[t][2] + bv.x), scale * (cs[t][3] + bv.y));
        }
    }
}

// ===========================================================================
// mma.sync attention — single-term fp16, KV tile 64, 4-stage cp.async
// ===========================================================================

#define OQH 0
#define OST 16384
#define STAGE_SZ 16384
#define SKH 0
#define SVH 8192
#define NSTAGE 4
#define ATTN_SMEM (OST + NSTAGE * STAGE_SZ)   /* 80 KB */
#define NKT (SEQ / 64)

__global__ __launch_bounds__(256, 2) void attn_kernel(
    const unsigned short* __restrict__ Qh,
    const unsigned short* __restrict__ Kh,
    const unsigned short* __restrict__ Vh,
    const float* __restrict__ relpos, float* __restrict__ Out)
{
    extern __shared__ char smp[];
    const uint32_t sb = smem_u32(smp);

    const int tid = threadIdx.x;
    const int w = tid >> 5;
    const int lane = tid & 31;
    const int b = blockIdx.z, h = blockIdx.y;
    const int q0 = blockIdx.x * 128;

    const float rb0 = relpos[h * 5 + 0];
    const float rb1 = relpos[h * 5 + 1];
    const float rb2 = relpos[h * 5 + 2];
    const float rb3 = relpos[h * 5 + 3];
    const float rb4 = relpos[h * 5 + 4];

    // Q tile load (128 rows x 128B, SW128)
    {
        const int row = tid >> 1;
        const int ch0 = (tid & 1) * 4;
        const size_t gb = (size_t)(b * SEQ + q0 + row) * DMODEL + h * HDIM + ch0 * 8;
#pragma unroll
        for (int ci = 0; ci < 4; ci++) {
            const uint32_t off = SW128((uint32_t)(row * 128 + (ch0 + ci) * 16));
            *(uint4*)(smp + OQH + off) = *(const uint4*)(Qh + gb + ci * 8);
        }
    }

    // K/V loader: 64 rows x 128B; thread -> row=tid>>2, 2x16B chunks
    const int krow = tid >> 2;
    const int kch = tid & 3;
    const size_t kgb0 = (size_t)(b * SEQ + krow) * DMODEL + h * HDIM + kch * 16;
    const uint32_t loff0 = SW128((uint32_t)(krow * 128 + kch * 32));
    const uint32_t loff1 = SW128((uint32_t)(krow * 128 + kch * 32 + 16));

    // prologue: stages 0..NSTAGE-2
#pragma unroll
    for (int s = 0; s < NSTAGE - 1; s++) {
        const uint32_t st = sb + OST + s * STAGE_SZ;
        const size_t gb = kgb0 + (size_t)(s * 64) * DMODEL;
        cpa16(st + SKH + loff0, Kh + gb);  cpa16(st + SKH + loff1, Kh + gb + 8);
        cpa16(st + SVH + loff0, Vh + gb);  cpa16(st + SVH + loff1, Vh + gb + 8);
        CP_COMMIT();
    }

    const uint32_t base_qa = (uint32_t)((16 * w + (lane & 15)) * 128 + 16 * (lane >> 4));
    const uint32_t base_kb = (uint32_t)(((lane & 7) + ((lane & 16) >> 1)) * 128 + ((lane >> 3) & 1) * 16);
    const uint32_t base_vb = (uint32_t)(((lane & 7) + (lane & 8)) * 128 + ((lane >> 4) & 1) * 16);

    float co[8][4];
#pragma unroll
    for (int i = 0; i < 8; i++)
#pragma unroll
        for (int j = 0; j < 4; j++) co[i][j] = 0.f;
    float sum0 = 0.f, sum1 = 0.f;

    const int r0g = q0 + 16 * w + (lane >> 2);
    const int kcol_off = 2 * (lane & 3);

    for (int kt = 0; kt < NKT; kt++) {
        const int k0 = kt * 64;

        CP_WAIT2();           // stage kt's group complete
        __syncthreads();      // all threads done with the stage being overwritten

        // issue stage kt+NSTAGE-1 (its buffer is now free)
        if (kt + NSTAGE - 1 < NKT) {
            const uint32_t st = sb + OST + ((kt + NSTAGE - 1) % NSTAGE) * STAGE_SZ;
            const size_t gb = kgb0 + (size_t)((kt + NSTAGE - 1) * 64) * DMODEL;
            cpa16(st + SKH + loff0, Kh + gb);  cpa16(st + SKH + loff1, Kh + gb + 8);
            cpa16(st + SVH + loff0, Vh + gb);  cpa16(st + SVH + loff1, Vh + gb + 8);
        }
        CP_COMMIT();

        const uint32_t st = sb + OST + (kt % NSTAGE) * STAGE_SZ;
        const uint32_t KHb = st + SKH, VHb = st + SVH;
        const uint32_t QHb = sb + OQH;

        // ---- S = Q @ K^T (fp16) ----
        float cs[8][4];
#pragma unroll
        for (int i = 0; i < 8; i++)
#pragma unroll
            for (int j = 0; j < 4; j++) cs[i][j] = 0.f;

#pragma unroll
        for (int c = 0; c < 4; c++) {
            uint32_t ah[4];
            ldsm4(ah, QHb + SW128(base_qa + 32 * c));
#pragma unroll
            for (int j2 = 0; j2 < 4; j2++) {
                uint32_t bh[4];
                ldsm4(bh, KHb + SW128(base_kb + 2048u * j2 + 32u * c));
                mmaf16(cs[2 * j2], ah, bh[0], bh[1]);
                mmaf16(cs[2 * j2 + 1], ah, bh[2], bh[3]);
            }
        }

        // ---- bias + exp + rowsum ----
        const bool uni = (k0 - (q0 + 127) > MAXREL) || ((k0 + 63) - q0 < -MAXREL);
        if (uni) {
            const float ub = (k0 > q0) ? rb4 : rb0;
#pragma unroll
            for (int j = 0; j < 8; j++) {
                cs[j][0] = __expf(cs[j][0] + ub);
                cs[j][1] = __expf(cs[j][1] + ub);
                cs[j][2] = __expf(cs[j][2] + ub);
                cs[j][3] = __expf(cs[j][3] + ub);
            }
        } else {
#pragma unroll
            for (int j = 0; j < 8; j++) {
                const int kc = k0 + 8 * j + kcol_off;
#pragma unroll
                for (int i = 0; i < 4; i++) {
                    const int rel = (kc + (i & 1)) - (r0g + (i >> 1) * 8);
                    const float bb = rel <= -MAXREL ? rb0 :
                                     rel >= MAXREL ? rb4 :
                                     rel == -1 ? rb1 : (rel == 0 ? rb2 : rb3);
                    cs[j][i] = __expf(cs[j][i] + bb);
                }
            }
        }
#pragma unroll
        for (int j = 0; j < 8; j++) {
            sum0 += cs[j][0] + cs[j][1];
            sum1 += cs[j][2] + cs[j][3];
        }

        // ---- O += P @ V (fp16) ----
#pragma unroll
        for (int kc = 0; kc < 4; kc++) {
            uint32_t ph[4];
            ph[0] = pkhf2(cs[2 * kc][0],     cs[2 * kc][1]);
            ph[1] = pkhf2(cs[2 * kc][2],     cs[2 * kc][3]);
            ph[2] = pkhf2(cs[2 * kc + 1][0], cs[2 * kc + 1][1]);
            ph[3] = pkhf2(cs[2 * kc + 1][2], cs[2 * kc + 1][3]);
#pragma unroll
            for (int jv = 0; jv < 4; jv++) {
                uint32_t vh[4];
                ldsm4t(vh, VHb + SW128(base_vb + 2048u * kc + 32u * jv));
                mmaf16(co[2 * jv], ph, vh[0], vh[1]);
                mmaf16(co[2 * jv + 1], ph, vh[2], vh[3]);
            }
        }
    }

    sum0 += __shfl_xor_sync(0xFFFFFFFFu, sum0, 1);
    sum0 += __shfl_xor_sync(0xFFFFFFFFu, sum0, 2);
    sum1 += __shfl_xor_sync(0xFFFFFFFFu, sum1, 1);
    sum1 += __shfl_xor_sync(0xFFFFFFFFu, sum1, 2);
    const float inv0 = 1.0f / sum0;
    const float inv1 = 1.0f / sum1;

    {
        float* O0 = Out + (size_t)(b * SEQ + r0g) * DMODEL + h * HDIM + kcol_off;
        float* O1 = O0 + 8 * DMODEL;
#pragma unroll
        for (int j = 0; j < 8; j++) {
            *(float2*)(O0 + 8 * j) = make_float2(co[j][0] * inv0, co[j][1] * inv0);
            *(float2*)(O1 + 8 * j) = make_float2(co[j][2] * inv1, co[j][3] * inv1);
        }
    }
}

// ---------------------------------------------------------------------------
extern "C" void kernel_launch(void* const* d_in, const int* in_sizes, int n_in,
                              void* d_out, int out_size)
{
    const float* q  = (const float*)d_in[0];
    const float* k  = (const float*)d_in[1];
    const float* v  = (const float*)d_in[2];
    const float* Wq = (const float*)d_in[3];
    const float* bq = (const float*)d_in[4];
    const float* Wk = (const float*)d_in[5];
    const float* bk = (const float*)d_in[6];
    const float* Wv = (const float*)d_in[7];
    const float* bv = (const float*)d_in[8];
    const float* Wo = (const float*)d_in[9];
    const float* bo = (const float*)d_in[10];
    const float* rp = (const float*)d_in[11];
    float* out = (float*)d_out;

    float *dA;
    unsigned short *dQh, *dKh, *dVh;
    cudaGetSymbolAddress((void**)&dA, g_A);
    cudaGetSymbolAddress((void**)&dQh, g_Qh);
    cudaGetSymbolAddress((void**)&dKh, g_Kh);
    cudaGetSymbolAddress((void**)&dVh, g_Vh);

    cudaFuncSetAttribute(attn_kernel, cudaFuncAttributeMaxDynamicSharedMemorySize,
                         ATTN_SMEM);

    dim3 gblk(256);
    dim3 ggrid(DMODEL / 128, MROWS / 128);   // (4, 64)

    gemm_bf16<<<ggrid, gblk>>>(q, Wq, bq, nullptr, dQh, 0.125f, 1);
    gemm_bf16<<<ggrid, gblk>>>(k, Wk, bk, nullptr, dKh, 1.0f, 1);
    gemm_bf16<<<ggrid, gblk>>>(v, Wv, bv, nullptr, dVh, 1.0f, 1);

    dim3 agrid(SEQ / 128, NHEAD, BATCH);     // (32, 8, 2)
    attn_kernel<<<agrid, gblk, ATTN_SMEM>>>(dQh, dKh, dVh, rp, dA);

    gemm_bf16<<<ggrid, gblk>>>(dA, Wo, bo, out, nullptr, 1.0f, 0);
}